// round 1
// baseline (speedup 1.0000x reference)
#include <cuda_runtime.h>
#include <cuda_bf16.h>
#include <math_constants.h>

// Problem constants
#define Bsz 8
#define T   2048
#define C   1024
#define H   128
#define NROWS (Bsz * T)   // 16384

// -------- scratch (no allocations allowed) --------
__device__ float g_k[NROWS * H];
__device__ float g_q[NROWS * H];
__device__ float g_v[NROWS * H];

// ============================================================
// Projection GEMM: out[M=16384, N=128] = x[16384,1024] @ W[1024,128]
// blockIdx.x in {0,1,2} selects (k,q,v). BM=128, BN=128, BK=16.
// 256 threads, 8x8 micro-tile per thread.
// ============================================================
#define PBK 16
#define AS_STRIDE 132   // padded, multiple of 4 for float4

__global__ __launch_bounds__(256) void proj_kernel(
    const float* __restrict__ x,
    const float* __restrict__ Wk,
    const float* __restrict__ Wq,
    const float* __restrict__ Wv)
{
    const float* W;
    float* out;
    if (blockIdx.x == 0)      { W = Wk; out = g_k; }
    else if (blockIdx.x == 1) { W = Wq; out = g_q; }
    else                      { W = Wv; out = g_v; }

    const int m0 = blockIdx.y * 128;

    __shared__ float As[PBK][AS_STRIDE];  // x tile, transposed: As[k][m]
    __shared__ float Bs[PBK][128];        // W tile: Bs[k][n]

    const int tid = threadIdx.x;
    const int tx = tid & 15;   // 0..15 -> N
    const int ty = tid >> 4;   // 0..15 -> M

    float acc[8][8];
#pragma unroll
    for (int i = 0; i < 8; i++)
#pragma unroll
        for (int j = 0; j < 8; j++) acc[i][j] = 0.f;

    for (int k0 = 0; k0 < C; k0 += PBK) {
        // A tile: 128 rows x 16 cols = 512 float4, 2 per thread
#pragma unroll
        for (int it = 0; it < 2; it++) {
            int idx = tid + it * 256;        // 0..511
            int row = idx >> 2;              // 0..127
            int c4  = idx & 3;               // 0..3
            float4 a = *(const float4*)(x + (size_t)(m0 + row) * C + k0 + c4 * 4);
            As[c4 * 4 + 0][row] = a.x;
            As[c4 * 4 + 1][row] = a.y;
            As[c4 * 4 + 2][row] = a.z;
            As[c4 * 4 + 3][row] = a.w;
        }
        // B tile: 16 rows x 128 cols = 512 float4, 2 per thread
#pragma unroll
        for (int it = 0; it < 2; it++) {
            int idx = tid + it * 256;
            int row = idx >> 5;              // 0..15
            int c4  = idx & 31;              // 0..31
            *(float4*)&Bs[row][c4 * 4] =
                *(const float4*)(W + (size_t)(k0 + row) * H + c4 * 4);
        }
        __syncthreads();

#pragma unroll
        for (int kk = 0; kk < PBK; kk++) {
            float4 a0 = *(const float4*)&As[kk][ty * 8];
            float4 a1 = *(const float4*)&As[kk][ty * 8 + 4];
            float4 b0 = *(const float4*)&Bs[kk][tx * 8];
            float4 b1 = *(const float4*)&Bs[kk][tx * 8 + 4];
            float a[8] = {a0.x, a0.y, a0.z, a0.w, a1.x, a1.y, a1.z, a1.w};
            float b[8] = {b0.x, b0.y, b0.z, b0.w, b1.x, b1.y, b1.z, b1.w};
#pragma unroll
            for (int i = 0; i < 8; i++)
#pragma unroll
                for (int j = 0; j < 8; j++)
                    acc[i][j] = fmaf(a[i], b[j], acc[i][j]);
        }
        __syncthreads();
    }

#pragma unroll
    for (int i = 0; i < 8; i++) {
        float* orow = out + (size_t)(m0 + ty * 8 + i) * H + tx * 8;
        *(float4*)(orow)     = make_float4(acc[i][0], acc[i][1], acc[i][2], acc[i][3]);
        *(float4*)(orow + 4) = make_float4(acc[i][4], acc[i][5], acc[i][6], acc[i][7]);
    }
}

// ============================================================
// Flash attention, fp32, causal. Q tile = 64 rows, KV tile = 64 rows.
// Block handles (batch b, q-tile pair {p, 31-p}) for load balance.
// 256 threads.
// ============================================================
#define QT 64
#define VSTRIDE 132
#define SSTRIDE 68

struct AttnSmem {
    float Qs[QT][VSTRIDE];
    float Ks[QT][VSTRIDE];
    float Vs[QT][VSTRIDE];
    float Ss[QT][SSTRIDE];
    float row_m[QT];
    float row_l[QT];
    float row_scale[QT];
};

__global__ __launch_bounds__(256) void attn_kernel(float* __restrict__ out)
{
    extern __shared__ char smem_raw[];
    AttnSmem& sm = *reinterpret_cast<AttnSmem*>(smem_raw);

    const int b    = blockIdx.y;
    const int pair = blockIdx.x;        // 0..15
    const int tid  = threadIdx.x;
    const int tx   = tid & 15;          // 0..15
    const int ty   = tid >> 4;          // 0..15

    const float* Qg = g_q + (size_t)b * T * H;
    const float* Kg = g_k + (size_t)b * T * H;
    const float* Vg = g_v + (size_t)b * T * H;

    for (int which = 0; which < 2; which++) {
        const int qt = which ? (31 - pair) : pair;

        // Load Q tile, fold in the C**0.5 = 32 scale (exact: power of 2)
        for (int i = tid; i < QT * 32; i += 256) {
            int row = i >> 5, c4 = i & 31;
            float4 qv = *(const float4*)(Qg + (size_t)(qt * QT + row) * H + c4 * 4);
            qv.x *= 32.f; qv.y *= 32.f; qv.z *= 32.f; qv.w *= 32.f;
            *(float4*)&sm.Qs[row][c4 * 4] = qv;
        }
        if (tid < QT) { sm.row_m[tid] = -CUDART_INF_F; sm.row_l[tid] = 0.f; }

        float o[4][8];
#pragma unroll
        for (int i = 0; i < 4; i++)
#pragma unroll
            for (int j = 0; j < 8; j++) o[i][j] = 0.f;

        __syncthreads();

        for (int kt = 0; kt <= qt; kt++) {
            // Load K, V tiles (each 64x128 fp32)
            for (int i = tid; i < QT * 32; i += 256) {
                int row = i >> 5, c4 = i & 31;
                *(float4*)&sm.Ks[row][c4 * 4] =
                    *(const float4*)(Kg + (size_t)(kt * QT + row) * H + c4 * 4);
                *(float4*)&sm.Vs[row][c4 * 4] =
                    *(const float4*)(Vg + (size_t)(kt * QT + row) * H + c4 * 4);
            }
            __syncthreads();

            // S = Qs * Ks^T : thread computes 4x4 (rows ty*4.., cols tx*4..)
            float s[4][4];
#pragma unroll
            for (int i = 0; i < 4; i++)
#pragma unroll
                for (int j = 0; j < 4; j++) s[i][j] = 0.f;

#pragma unroll 4
            for (int h4 = 0; h4 < 32; h4++) {
                float4 qv[4], kv[4];
#pragma unroll
                for (int i = 0; i < 4; i++) qv[i] = *(const float4*)&sm.Qs[ty * 4 + i][h4 * 4];
#pragma unroll
                for (int j = 0; j < 4; j++) kv[j] = *(const float4*)&sm.Ks[tx * 4 + j][h4 * 4];
#pragma unroll
                for (int i = 0; i < 4; i++)
#pragma unroll
                    for (int j = 0; j < 4; j++) {
                        s[i][j] = fmaf(qv[i].x, kv[j].x, s[i][j]);
                        s[i][j] = fmaf(qv[i].y, kv[j].y, s[i][j]);
                        s[i][j] = fmaf(qv[i].z, kv[j].z, s[i][j]);
                        s[i][j] = fmaf(qv[i].w, kv[j].w, s[i][j]);
                    }
            }

            if (kt == qt) {
                // diagonal tile: mask key index > query index
#pragma unroll
                for (int i = 0; i < 4; i++)
#pragma unroll
                    for (int j = 0; j < 4; j++)
                        if (tx * 4 + j > ty * 4 + i) s[i][j] = -CUDART_INF_F;
            }
#pragma unroll
            for (int i = 0; i < 4; i++)
#pragma unroll
                for (int j = 0; j < 4; j++)
                    sm.Ss[ty * 4 + i][tx * 4 + j] = s[i][j];
            __syncthreads();

            // Online softmax: 4 threads per row (row = tid>>2, quad = tid&3)
            {
                int row  = tid >> 2;
                int quad = tid & 3;
                float mx = -CUDART_INF_F;
#pragma unroll
                for (int c = 0; c < 16; c++)
                    mx = fmaxf(mx, sm.Ss[row][quad * 16 + c]);
                mx = fmaxf(mx, __shfl_xor_sync(0xFFFFFFFFu, mx, 1));
                mx = fmaxf(mx, __shfl_xor_sync(0xFFFFFFFFu, mx, 2));

                float m_old = sm.row_m[row];
                float m_new = fmaxf(m_old, mx);
                float sumv = 0.f;
#pragma unroll
                for (int c = 0; c < 16; c++) {
                    float p = __expf(sm.Ss[row][quad * 16 + c] - m_new);
                    sm.Ss[row][quad * 16 + c] = p;
                    sumv += p;
                }
                sumv += __shfl_xor_sync(0xFFFFFFFFu, sumv, 1);
                sumv += __shfl_xor_sync(0xFFFFFFFFu, sumv, 2);
                if (quad == 0) {
                    float sc = __expf(m_old - m_new);   // exp(-inf)=0 on first tile
                    sm.row_scale[row] = sc;
                    sm.row_l[row] = sm.row_l[row] * sc + sumv;
                    sm.row_m[row] = m_new;
                }
            }
            __syncthreads();

            // O = O*scale + P @ V : thread owns rows ty*4.., cols tx*8..
            {
                float scr[4];
#pragma unroll
                for (int i = 0; i < 4; i++) scr[i] = sm.row_scale[ty * 4 + i];
#pragma unroll
                for (int i = 0; i < 4; i++)
#pragma unroll
                    for (int j = 0; j < 8; j++) o[i][j] *= scr[i];

#pragma unroll 4
                for (int kr = 0; kr < QT; kr++) {
                    float p[4];
#pragma unroll
                    for (int i = 0; i < 4; i++) p[i] = sm.Ss[ty * 4 + i][kr];
                    float4 v0 = *(const float4*)&sm.Vs[kr][tx * 8];
                    float4 v1 = *(const float4*)&sm.Vs[kr][tx * 8 + 4];
#pragma unroll
                    for (int i = 0; i < 4; i++) {
                        o[i][0] = fmaf(p[i], v0.x, o[i][0]);
                        o[i][1] = fmaf(p[i], v0.y, o[i][1]);
                        o[i][2] = fmaf(p[i], v0.z, o[i][2]);
                        o[i][3] = fmaf(p[i], v0.w, o[i][3]);
                        o[i][4] = fmaf(p[i], v1.x, o[i][4]);
                        o[i][5] = fmaf(p[i], v1.y, o[i][5]);
                        o[i][6] = fmaf(p[i], v1.z, o[i][6]);
                        o[i][7] = fmaf(p[i], v1.w, o[i][7]);
                    }
                }
            }
            __syncthreads();   // protect Ks/Vs/Ss before next tile load
        }

        // Finalize: divide by l and store
#pragma unroll
        for (int i = 0; i < 4; i++) {
            float inv = 1.f / sm.row_l[ty * 4 + i];
            float* orow = out + (size_t)b * T * H + (size_t)(qt * QT + ty * 4 + i) * H + tx * 8;
            *(float4*)(orow)     = make_float4(o[i][0] * inv, o[i][1] * inv, o[i][2] * inv, o[i][3] * inv);
            *(float4*)(orow + 4) = make_float4(o[i][4] * inv, o[i][5] * inv, o[i][6] * inv, o[i][7] * inv);
        }
        __syncthreads();   // state reset of next q-tile must not race readers
    }
}

// ============================================================
extern "C" void kernel_launch(void* const* d_in, const int* in_sizes, int n_in,
                              void* d_out, int out_size)
{
    const float* x  = (const float*)d_in[0];
    const float* Wk = (const float*)d_in[1];
    const float* Wq = (const float*)d_in[2];
    const float* Wv = (const float*)d_in[3];
    float* out = (float*)d_out;

    static bool attr_set = false;
    // idempotent, deterministic; needed because AttnSmem > 48KB
    cudaFuncSetAttribute(attn_kernel,
                         cudaFuncAttributeMaxDynamicSharedMemorySize,
                         (int)sizeof(AttnSmem));

    proj_kernel<<<dim3(3, NROWS / 128), 256>>>(x, Wk, Wq, Wv);
    attn_kernel<<<dim3(16, Bsz), 256, sizeof(AttnSmem)>>>(out);
    (void)attr_set; (void)in_sizes; (void)n_in; (void)out_size;
}

// round 2
// speedup vs baseline: 1.0862x; 1.0862x over previous
#include <cuda_runtime.h>
#include <cuda_bf16.h>
#include <math_constants.h>

// Problem constants
#define Bsz 8
#define T   2048
#define C   1024
#define H   128
#define NROWS (Bsz * T)   // 16384

// -------- scratch (no allocations allowed) --------
__device__ float g_k[NROWS * H];
__device__ float g_q[NROWS * H];
__device__ float g_v[NROWS * H];

// -------- packed f32x2 helpers (B300 FFMA2 path, PTX-only) --------
__device__ __forceinline__ unsigned long long pk2(float x, float y) {
    unsigned long long r;
    asm("mov.b64 %0, {%1, %2};" : "=l"(r)
        : "r"(__float_as_uint(x)), "r"(__float_as_uint(y)));
    return r;
}
__device__ __forceinline__ void fma2(unsigned long long& d,
                                     unsigned long long a,
                                     unsigned long long b) {
    asm("fma.rn.f32x2 %0, %1, %2, %0;" : "+l"(d) : "l"(a), "l"(b));
}
__device__ __forceinline__ void mul2(unsigned long long& d,
                                     unsigned long long a,
                                     unsigned long long b) {
    asm("mul.rn.f32x2 %0, %1, %2;" : "=l"(d) : "l"(a), "l"(b));
}
__device__ __forceinline__ float2 up2(unsigned long long v) {
    float2 f;
    unsigned lo, hi;
    asm("mov.b64 {%0, %1}, %2;" : "=r"(lo), "=r"(hi) : "l"(v));
    f.x = __uint_as_float(lo); f.y = __uint_as_float(hi);
    return f;
}

// ============================================================
// Projection GEMM: out[16384,128] = x[16384,1024] @ W[1024,128]
// blockIdx.x in {0,1,2} selects (k,q,v). BM=128, BN=128, BK=16.
// 256 threads, 8x8 micro-tile per thread, f32x2 packed FMA.
// ============================================================
#define PBK 16
#define AS_STRIDE 132

__global__ __launch_bounds__(256) void proj_kernel(
    const float* __restrict__ x,
    const float* __restrict__ Wk,
    const float* __restrict__ Wq,
    const float* __restrict__ Wv)
{
    const float* W;
    float* out;
    if (blockIdx.x == 0)      { W = Wk; out = g_k; }
    else if (blockIdx.x == 1) { W = Wq; out = g_q; }
    else                      { W = Wv; out = g_v; }

    const int m0 = blockIdx.y * 128;

    __shared__ float As[PBK][AS_STRIDE];  // x tile transposed: As[k][m]
    __shared__ float Bs[PBK][128];        // W tile: Bs[k][n]

    const int tid = threadIdx.x;
    const int tx = tid & 15;
    const int ty = tid >> 4;

    unsigned long long acc2[8][4];
#pragma unroll
    for (int i = 0; i < 8; i++)
#pragma unroll
        for (int j = 0; j < 4; j++) acc2[i][j] = 0ull;

    for (int k0 = 0; k0 < C; k0 += PBK) {
#pragma unroll
        for (int it = 0; it < 2; it++) {
            int idx = tid + it * 256;
            int row = idx >> 2;
            int c4  = idx & 3;
            float4 a = *(const float4*)(x + (size_t)(m0 + row) * C + k0 + c4 * 4);
            As[c4 * 4 + 0][row] = a.x;
            As[c4 * 4 + 1][row] = a.y;
            As[c4 * 4 + 2][row] = a.z;
            As[c4 * 4 + 3][row] = a.w;
        }
#pragma unroll
        for (int it = 0; it < 2; it++) {
            int idx = tid + it * 256;
            int row = idx >> 5;
            int c4  = idx & 31;
            *(float4*)&Bs[row][c4 * 4] =
                *(const float4*)(W + (size_t)(k0 + row) * H + c4 * 4);
        }
        __syncthreads();

#pragma unroll
        for (int kk = 0; kk < PBK; kk++) {
            float4 a0 = *(const float4*)&As[kk][ty * 8];
            float4 a1 = *(const float4*)&As[kk][ty * 8 + 4];
            float a[8] = {a0.x, a0.y, a0.z, a0.w, a1.x, a1.y, a1.z, a1.w};
            ulonglong2 bq0 = *(const ulonglong2*)&Bs[kk][tx * 8];
            ulonglong2 bq1 = *(const ulonglong2*)&Bs[kk][tx * 8 + 4];
#pragma unroll
            for (int i = 0; i < 8; i++) {
                unsigned long long aa = pk2(a[i], a[i]);
                fma2(acc2[i][0], aa, bq0.x);
                fma2(acc2[i][1], aa, bq0.y);
                fma2(acc2[i][2], aa, bq1.x);
                fma2(acc2[i][3], aa, bq1.y);
            }
        }
        __syncthreads();
    }

#pragma unroll
    for (int i = 0; i < 8; i++) {
        float* orow = out + (size_t)(m0 + ty * 8 + i) * H + tx * 8;
        float2 p0 = up2(acc2[i][0]), p1 = up2(acc2[i][1]);
        float2 p2 = up2(acc2[i][2]), p3 = up2(acc2[i][3]);
        *(float4*)(orow)     = make_float4(p0.x, p0.y, p1.x, p1.y);
        *(float4*)(orow + 4) = make_float4(p2.x, p2.y, p3.x, p3.y);
    }
}

// ============================================================
// Flash attention, fp32 (f32x2 packed), causal.
// Q tile = 64, KV tile = 64, 256 threads, 2 CTAs/SM.
// K stored transposed in smem (conflict-free); P overlays Kt.
// Grid: 256 blocks, LPT order (heaviest q-tiles first).
// ============================================================
#define QT 64
#define QSTR 132
#define KTSTR 68

struct AttnSmem {
    float Qs[QT][QSTR];     // q rows, row-major (broadcast reads OK)
    float Kt[H][KTSTR];     // K transposed: Kt[h][krow]; reused as P[64][68]
    float Vs[QT][H];        // V row-major, stride 128 (conflict-free)
    float row_m[QT];
    float row_l[QT];
    float row_scale[QT];
};

__global__ __launch_bounds__(256, 2) void attn_kernel(float* __restrict__ out)
{
    extern __shared__ char smem_raw[];
    AttnSmem& sm = *reinterpret_cast<AttnSmem*>(smem_raw);

    const int lin = blockIdx.x;          // 0..255
    const int b   = lin & 7;
    const int qt  = 31 - (lin >> 3);     // heavy tiles launch first
    const int tid = threadIdx.x;
    const int tx  = tid & 15;
    const int ty  = tid >> 4;

    const float* Qg = g_q + (size_t)b * T * H + (size_t)qt * QT * H;
    const float* Kg = g_k + (size_t)b * T * H;
    const float* Vg = g_v + (size_t)b * T * H;

    // Load Q tile, fold the C**0.5 = 32 scale (exact power of 2)
#pragma unroll
    for (int r = 0; r < 8; r++) {
        int idx = tid + r * 256;
        int row = idx >> 5, c4 = idx & 31;
        float4 qv = *(const float4*)(Qg + (size_t)row * H + c4 * 4);
        qv.x *= 32.f; qv.y *= 32.f; qv.z *= 32.f; qv.w *= 32.f;
        *(float4*)&sm.Qs[row][c4 * 4] = qv;
    }
    if (tid < QT) { sm.row_m[tid] = -CUDART_INF_F; sm.row_l[tid] = 0.f; }

    unsigned long long o2[4][4];
#pragma unroll
    for (int i = 0; i < 4; i++)
#pragma unroll
        for (int j = 0; j < 4; j++) o2[i][j] = 0ull;

    __syncthreads();

    for (int kt = 0; kt <= qt; kt++) {
        const float* Kt_g = Kg + (size_t)kt * QT * H;
        const float* Vt_g = Vg + (size_t)kt * QT * H;

        // K: strided gmem read (lane-per-row) -> conflict-free transposed store.
        // V: coalesced.
#pragma unroll
        for (int r = 0; r < 8; r++) {
            int idx  = tid + r * 256;
            int krow = idx & 63, kc4 = idx >> 6;
            float4 kv = *(const float4*)(Kt_g + (size_t)krow * H + kc4 * 4);
            sm.Kt[kc4 * 4 + 0][krow] = kv.x;
            sm.Kt[kc4 * 4 + 1][krow] = kv.y;
            sm.Kt[kc4 * 4 + 2][krow] = kv.z;
            sm.Kt[kc4 * 4 + 3][krow] = kv.w;
            int vrow = idx >> 5, vc4 = idx & 31;
            *(float4*)&sm.Vs[vrow][vc4 * 4] =
                *(const float4*)(Vt_g + (size_t)vrow * H + vc4 * 4);
        }
        __syncthreads();   // A: tiles ready

        // ---- S = Q K^T (f32x2 packed: s2[i][jp] = cols 2jp,2jp+1 of tx*4 base)
        unsigned long long s2[4][2];
#pragma unroll
        for (int i = 0; i < 4; i++) { s2[i][0] = 0ull; s2[i][1] = 0ull; }

#pragma unroll 4
        for (int h4 = 0; h4 < 32; h4++) {
            ulonglong2 kq0 = *(const ulonglong2*)&sm.Kt[h4 * 4 + 0][tx * 4];
            ulonglong2 kq1 = *(const ulonglong2*)&sm.Kt[h4 * 4 + 1][tx * 4];
            ulonglong2 kq2 = *(const ulonglong2*)&sm.Kt[h4 * 4 + 2][tx * 4];
            ulonglong2 kq3 = *(const ulonglong2*)&sm.Kt[h4 * 4 + 3][tx * 4];
#pragma unroll
            for (int i = 0; i < 4; i++) {
                float4 qv = *(const float4*)&sm.Qs[ty * 4 + i][h4 * 4];
                unsigned long long aa;
                aa = pk2(qv.x, qv.x); fma2(s2[i][0], aa, kq0.x); fma2(s2[i][1], aa, kq0.y);
                aa = pk2(qv.y, qv.y); fma2(s2[i][0], aa, kq1.x); fma2(s2[i][1], aa, kq1.y);
                aa = pk2(qv.z, qv.z); fma2(s2[i][0], aa, kq2.x); fma2(s2[i][1], aa, kq2.y);
                aa = pk2(qv.w, qv.w); fma2(s2[i][0], aa, kq3.x); fma2(s2[i][1], aa, kq3.y);
            }
        }

        // unpack + causal mask on diagonal tile
        float sv[4][4];
#pragma unroll
        for (int i = 0; i < 4; i++) {
            float2 t0 = up2(s2[i][0]), t1 = up2(s2[i][1]);
            sv[i][0] = t0.x; sv[i][1] = t0.y; sv[i][2] = t1.x; sv[i][3] = t1.y;
        }
        if (kt == qt) {
#pragma unroll
            for (int i = 0; i < 4; i++)
#pragma unroll
                for (int j = 0; j < 4; j++)
                    if (tx * 4 + j > ty * 4 + i) sv[i][j] = -CUDART_INF_F;
        }
        __syncthreads();   // B: all Kt reads done, safe to overlay P

        float (*P)[KTSTR] = reinterpret_cast<float(*)[KTSTR]>(sm.Kt);
#pragma unroll
        for (int i = 0; i < 4; i++)
            *(float4*)&P[ty * 4 + i][tx * 4] =
                make_float4(sv[i][0], sv[i][1], sv[i][2], sv[i][3]);
        __syncthreads();   // C: P visible

        // ---- online softmax: 4 threads per row
        {
            int row  = tid >> 2;
            int quad = tid & 3;
            float mx = -CUDART_INF_F;
#pragma unroll
            for (int c = 0; c < 16; c++)
                mx = fmaxf(mx, P[row][quad * 16 + c]);
            mx = fmaxf(mx, __shfl_xor_sync(0xFFFFFFFFu, mx, 1));
            mx = fmaxf(mx, __shfl_xor_sync(0xFFFFFFFFu, mx, 2));

            float m_old = sm.row_m[row];
            float m_new = fmaxf(m_old, mx);
            float sumv = 0.f;
#pragma unroll
            for (int c = 0; c < 16; c++) {
                float p = __expf(P[row][quad * 16 + c] - m_new);
                P[row][quad * 16 + c] = p;
                sumv += p;
            }
            sumv += __shfl_xor_sync(0xFFFFFFFFu, sumv, 1);
            sumv += __shfl_xor_sync(0xFFFFFFFFu, sumv, 2);
            if (quad == 0) {
                float sc = __expf(m_old - m_new);  // 0 on first tile
                sm.row_scale[row] = sc;
                sm.row_l[row] = sm.row_l[row] * sc + sumv;
                sm.row_m[row] = m_new;
            }
        }
        __syncthreads();   // D: P + row_scale ready

        // ---- O = O*scale + P @ V (f32x2 packed)
        {
#pragma unroll
            for (int i = 0; i < 4; i++) {
                float scr = sm.row_scale[ty * 4 + i];
                unsigned long long sc2 = pk2(scr, scr);
#pragma unroll
                for (int j = 0; j < 4; j++) {
                    unsigned long long t = o2[i][j];
                    mul2(t, t, sc2);
                    o2[i][j] = t;
                }
            }
#pragma unroll 2
            for (int kr4 = 0; kr4 < 16; kr4++) {
                float p4[4][4];
#pragma unroll
                for (int i = 0; i < 4; i++)
                    *(float4*)p4[i] = *(const float4*)&P[ty * 4 + i][kr4 * 4];
#pragma unroll
                for (int t = 0; t < 4; t++) {
                    int kr = kr4 * 4 + t;
                    ulonglong2 v0 = *(const ulonglong2*)&sm.Vs[kr][tx * 8];
                    ulonglong2 v1 = *(const ulonglong2*)&sm.Vs[kr][tx * 8 + 4];
#pragma unroll
                    for (int i = 0; i < 4; i++) {
                        unsigned long long pi = pk2(p4[i][t], p4[i][t]);
                        fma2(o2[i][0], pi, v0.x);
                        fma2(o2[i][1], pi, v0.y);
                        fma2(o2[i][2], pi, v1.x);
                        fma2(o2[i][3], pi, v1.y);
                    }
                }
            }
        }
        __syncthreads();   // E: P/Vs free for next tile
    }

    // finalize: divide by l, store
#pragma unroll
    for (int i = 0; i < 4; i++) {
        float inv = 1.f / sm.row_l[ty * 4 + i];
        float* orow = out + (size_t)b * T * H
                    + (size_t)(qt * QT + ty * 4 + i) * H + tx * 8;
        float2 p0 = up2(o2[i][0]), p1 = up2(o2[i][1]);
        float2 p2 = up2(o2[i][2]), p3 = up2(o2[i][3]);
        *(float4*)(orow)     = make_float4(p0.x * inv, p0.y * inv, p1.x * inv, p1.y * inv);
        *(float4*)(orow + 4) = make_float4(p2.x * inv, p2.y * inv, p3.x * inv, p3.y * inv);
    }
}

// ============================================================
extern "C" void kernel_launch(void* const* d_in, const int* in_sizes, int n_in,
                              void* d_out, int out_size)
{
    const float* x  = (const float*)d_in[0];
    const float* Wk = (const float*)d_in[1];
    const float* Wq = (const float*)d_in[2];
    const float* Wv = (const float*)d_in[3];
    float* out = (float*)d_out;

    cudaFuncSetAttribute(attn_kernel,
                         cudaFuncAttributeMaxDynamicSharedMemorySize,
                         (int)sizeof(AttnSmem));

    proj_kernel<<<dim3(3, NROWS / 128), 256>>>(x, Wk, Wq, Wv);
    attn_kernel<<<dim3(256, 1), 256, sizeof(AttnSmem)>>>(out);
    (void)in_sizes; (void)n_in; (void)out_size;
}

// round 3
// speedup vs baseline: 1.0866x; 1.0003x over previous
#include <cuda_runtime.h>
#include <cuda_bf16.h>
#include <math_constants.h>

// Problem constants
#define Bsz 8
#define T   2048
#define C   1024
#define H   128
#define NROWS (Bsz * T)   // 16384

// -------- scratch (no allocations allowed) --------
__device__ float g_k[NROWS * H];
__device__ float g_q[NROWS * H];
__device__ float g_v[NROWS * H];

// -------- packed f32x2 helpers (B300 FFMA2 path, PTX-only) --------
__device__ __forceinline__ unsigned long long pk2(float x, float y) {
    unsigned long long r;
    asm("mov.b64 %0, {%1, %2};" : "=l"(r)
        : "r"(__float_as_uint(x)), "r"(__float_as_uint(y)));
    return r;
}
__device__ __forceinline__ void fma2(unsigned long long& d,
                                     unsigned long long a,
                                     unsigned long long b) {
    asm("fma.rn.f32x2 %0, %1, %2, %0;" : "+l"(d) : "l"(a), "l"(b));
}
__device__ __forceinline__ void mul2(unsigned long long& d,
                                     unsigned long long a,
                                     unsigned long long b) {
    asm("mul.rn.f32x2 %0, %1, %2;" : "=l"(d) : "l"(a), "l"(b));
}
__device__ __forceinline__ float2 up2(unsigned long long v) {
    float2 f;
    unsigned lo, hi;
    asm("mov.b64 {%0, %1}, %2;" : "=r"(lo), "=r"(hi) : "l"(v));
    f.x = __uint_as_float(lo); f.y = __uint_as_float(hi);
    return f;
}

// ============================================================
// Projection GEMM: out[16384,128] = x[16384,1024] @ W[1024,128]
// blockIdx.x in {0,1,2} selects (k,q,v). BM=128, BN=128, BK=16.
// 256 threads, 8x8 micro-tile per thread, f32x2 packed FMA.
// ============================================================
#define PBK 16
#define AS_STRIDE 132

__global__ __launch_bounds__(256) void proj_kernel(
    const float* __restrict__ x,
    const float* __restrict__ Wk,
    const float* __restrict__ Wq,
    const float* __restrict__ Wv)
{
    const float* W;
    float* out;
    if (blockIdx.x == 0)      { W = Wk; out = g_k; }
    else if (blockIdx.x == 1) { W = Wq; out = g_q; }
    else                      { W = Wv; out = g_v; }

    const int m0 = blockIdx.y * 128;

    __shared__ float As[PBK][AS_STRIDE];  // x tile transposed: As[k][m]
    __shared__ float Bs[PBK][128];        // W tile: Bs[k][n]

    const int tid = threadIdx.x;
    const int tx = tid & 15;
    const int ty = tid >> 4;

    unsigned long long acc2[8][4];
#pragma unroll
    for (int i = 0; i < 8; i++)
#pragma unroll
        for (int j = 0; j < 4; j++) acc2[i][j] = 0ull;

    for (int k0 = 0; k0 < C; k0 += PBK) {
#pragma unroll
        for (int it = 0; it < 2; it++) {
            int idx = tid + it * 256;
            int row = idx >> 2;
            int c4  = idx & 3;
            float4 a = *(const float4*)(x + (size_t)(m0 + row) * C + k0 + c4 * 4);
            As[c4 * 4 + 0][row] = a.x;
            As[c4 * 4 + 1][row] = a.y;
            As[c4 * 4 + 2][row] = a.z;
            As[c4 * 4 + 3][row] = a.w;
        }
#pragma unroll
        for (int it = 0; it < 2; it++) {
            int idx = tid + it * 256;
            int row = idx >> 5;
            int c4  = idx & 31;
            *(float4*)&Bs[row][c4 * 4] =
                *(const float4*)(W + (size_t)(k0 + row) * H + c4 * 4);
        }
        __syncthreads();

#pragma unroll
        for (int kk = 0; kk < PBK; kk++) {
            float4 a0 = *(const float4*)&As[kk][ty * 8];
            float4 a1 = *(const float4*)&As[kk][ty * 8 + 4];
            float a[8] = {a0.x, a0.y, a0.z, a0.w, a1.x, a1.y, a1.z, a1.w};
            ulonglong2 bq0 = *(const ulonglong2*)&Bs[kk][tx * 8];
            ulonglong2 bq1 = *(const ulonglong2*)&Bs[kk][tx * 8 + 4];
#pragma unroll
            for (int i = 0; i < 8; i++) {
                unsigned long long aa = pk2(a[i], a[i]);
                fma2(acc2[i][0], aa, bq0.x);
                fma2(acc2[i][1], aa, bq0.y);
                fma2(acc2[i][2], aa, bq1.x);
                fma2(acc2[i][3], aa, bq1.y);
            }
        }
        __syncthreads();
    }

#pragma unroll
    for (int i = 0; i < 8; i++) {
        float* orow = out + (size_t)(m0 + ty * 8 + i) * H + tx * 8;
        float2 p0 = up2(acc2[i][0]), p1 = up2(acc2[i][1]);
        float2 p2 = up2(acc2[i][2]), p3 = up2(acc2[i][3]);
        *(float4*)(orow)     = make_float4(p0.x, p0.y, p1.x, p1.y);
        *(float4*)(orow + 4) = make_float4(p2.x, p2.y, p3.x, p3.y);
    }
}

// ============================================================
// Flash attention, fp32 (f32x2 packed), causal.
// Q tile = 64, KV tile = 64, 256 threads, 2 CTAs/SM.
// K stored transposed in smem (conflict-free); P overlays Kt.
// Grid: 256 blocks, LPT order (heaviest q-tiles first).
// ============================================================
#define QT 64
#define QSTR 132
#define KTSTR 68

struct AttnSmem {
    float Qs[QT][QSTR];     // q rows, row-major (broadcast reads OK)
    float Kt[H][KTSTR];     // K transposed: Kt[h][krow]; reused as P[64][68]
    float Vs[QT][H];        // V row-major, stride 128 (conflict-free)
    float row_m[QT];
    float row_l[QT];
    float row_scale[QT];
};

__global__ __launch_bounds__(256, 2) void attn_kernel(float* __restrict__ out)
{
    extern __shared__ char smem_raw[];
    AttnSmem& sm = *reinterpret_cast<AttnSmem*>(smem_raw);

    const int lin = blockIdx.x;          // 0..255
    const int b   = lin & 7;
    const int qt  = 31 - (lin >> 3);     // heavy tiles launch first
    const int tid = threadIdx.x;
    const int tx  = tid & 15;
    const int ty  = tid >> 4;

    const float* Qg = g_q + (size_t)b * T * H + (size_t)qt * QT * H;
    const float* Kg = g_k + (size_t)b * T * H;
    const float* Vg = g_v + (size_t)b * T * H;

    // Load Q tile, fold the C**0.5 = 32 scale (exact power of 2)
#pragma unroll
    for (int r = 0; r < 8; r++) {
        int idx = tid + r * 256;
        int row = idx >> 5, c4 = idx & 31;
        float4 qv = *(const float4*)(Qg + (size_t)row * H + c4 * 4);
        qv.x *= 32.f; qv.y *= 32.f; qv.z *= 32.f; qv.w *= 32.f;
        *(float4*)&sm.Qs[row][c4 * 4] = qv;
    }
    if (tid < QT) { sm.row_m[tid] = -CUDART_INF_F; sm.row_l[tid] = 0.f; }

    unsigned long long o2[4][4];
#pragma unroll
    for (int i = 0; i < 4; i++)
#pragma unroll
        for (int j = 0; j < 4; j++) o2[i][j] = 0ull;

    __syncthreads();

    for (int kt = 0; kt <= qt; kt++) {
        const float* Kt_g = Kg + (size_t)kt * QT * H;
        const float* Vt_g = Vg + (size_t)kt * QT * H;

        // K: strided gmem read (lane-per-row) -> conflict-free transposed store.
        // V: coalesced.
#pragma unroll
        for (int r = 0; r < 8; r++) {
            int idx  = tid + r * 256;
            int krow = idx & 63, kc4 = idx >> 6;
            float4 kv = *(const float4*)(Kt_g + (size_t)krow * H + kc4 * 4);
            sm.Kt[kc4 * 4 + 0][krow] = kv.x;
            sm.Kt[kc4 * 4 + 1][krow] = kv.y;
            sm.Kt[kc4 * 4 + 2][krow] = kv.z;
            sm.Kt[kc4 * 4 + 3][krow] = kv.w;
            int vrow = idx >> 5, vc4 = idx & 31;
            *(float4*)&sm.Vs[vrow][vc4 * 4] =
                *(const float4*)(Vt_g + (size_t)vrow * H + vc4 * 4);
        }
        __syncthreads();   // A: tiles ready

        // ---- S = Q K^T (f32x2 packed: s2[i][jp] = cols 2jp,2jp+1 of tx*4 base)
        unsigned long long s2[4][2];
#pragma unroll
        for (int i = 0; i < 4; i++) { s2[i][0] = 0ull; s2[i][1] = 0ull; }

#pragma unroll 4
        for (int h4 = 0; h4 < 32; h4++) {
            ulonglong2 kq0 = *(const ulonglong2*)&sm.Kt[h4 * 4 + 0][tx * 4];
            ulonglong2 kq1 = *(const ulonglong2*)&sm.Kt[h4 * 4 + 1][tx * 4];
            ulonglong2 kq2 = *(const ulonglong2*)&sm.Kt[h4 * 4 + 2][tx * 4];
            ulonglong2 kq3 = *(const ulonglong2*)&sm.Kt[h4 * 4 + 3][tx * 4];
#pragma unroll
            for (int i = 0; i < 4; i++) {
                float4 qv = *(const float4*)&sm.Qs[ty * 4 + i][h4 * 4];
                unsigned long long aa;
                aa = pk2(qv.x, qv.x); fma2(s2[i][0], aa, kq0.x); fma2(s2[i][1], aa, kq0.y);
                aa = pk2(qv.y, qv.y); fma2(s2[i][0], aa, kq1.x); fma2(s2[i][1], aa, kq1.y);
                aa = pk2(qv.z, qv.z); fma2(s2[i][0], aa, kq2.x); fma2(s2[i][1], aa, kq2.y);
                aa = pk2(qv.w, qv.w); fma2(s2[i][0], aa, kq3.x); fma2(s2[i][1], aa, kq3.y);
            }
        }

        // unpack + causal mask on diagonal tile
        float sv[4][4];
#pragma unroll
        for (int i = 0; i < 4; i++) {
            float2 t0 = up2(s2[i][0]), t1 = up2(s2[i][1]);
            sv[i][0] = t0.x; sv[i][1] = t0.y; sv[i][2] = t1.x; sv[i][3] = t1.y;
        }
        if (kt == qt) {
#pragma unroll
            for (int i = 0; i < 4; i++)
#pragma unroll
                for (int j = 0; j < 4; j++)
                    if (tx * 4 + j > ty * 4 + i) sv[i][j] = -CUDART_INF_F;
        }
        __syncthreads();   // B: all Kt reads done, safe to overlay P

        float (*P)[KTSTR] = reinterpret_cast<float(*)[KTSTR]>(sm.Kt);
#pragma unroll
        for (int i = 0; i < 4; i++)
            *(float4*)&P[ty * 4 + i][tx * 4] =
                make_float4(sv[i][0], sv[i][1], sv[i][2], sv[i][3]);
        __syncthreads();   // C: P visible

        // ---- online softmax: 4 threads per row
        {
            int row  = tid >> 2;
            int quad = tid & 3;
            float mx = -CUDART_INF_F;
#pragma unroll
            for (int c = 0; c < 16; c++)
                mx = fmaxf(mx, P[row][quad * 16 + c]);
            mx = fmaxf(mx, __shfl_xor_sync(0xFFFFFFFFu, mx, 1));
            mx = fmaxf(mx, __shfl_xor_sync(0xFFFFFFFFu, mx, 2));

            float m_old = sm.row_m[row];
            float m_new = fmaxf(m_old, mx);
            float sumv = 0.f;
#pragma unroll
            for (int c = 0; c < 16; c++) {
                float p = __expf(P[row][quad * 16 + c] - m_new);
                P[row][quad * 16 + c] = p;
                sumv += p;
            }
            sumv += __shfl_xor_sync(0xFFFFFFFFu, sumv, 1);
            sumv += __shfl_xor_sync(0xFFFFFFFFu, sumv, 2);
            if (quad == 0) {
                float sc = __expf(m_old - m_new);  // 0 on first tile
                sm.row_scale[row] = sc;
                sm.row_l[row] = sm.row_l[row] * sc + sumv;
                sm.row_m[row] = m_new;
            }
        }
        __syncthreads();   // D: P + row_scale ready

        // ---- O = O*scale + P @ V (f32x2 packed)
        {
#pragma unroll
            for (int i = 0; i < 4; i++) {
                float scr = sm.row_scale[ty * 4 + i];
                unsigned long long sc2 = pk2(scr, scr);
#pragma unroll
                for (int j = 0; j < 4; j++) {
                    unsigned long long t = o2[i][j];
                    mul2(t, t, sc2);
                    o2[i][j] = t;
                }
            }
#pragma unroll 2
            for (int kr4 = 0; kr4 < 16; kr4++) {
                float p4[4][4];
#pragma unroll
                for (int i = 0; i < 4; i++)
                    *(float4*)p4[i] = *(const float4*)&P[ty * 4 + i][kr4 * 4];
#pragma unroll
                for (int t = 0; t < 4; t++) {
                    int kr = kr4 * 4 + t;
                    ulonglong2 v0 = *(const ulonglong2*)&sm.Vs[kr][tx * 8];
                    ulonglong2 v1 = *(const ulonglong2*)&sm.Vs[kr][tx * 8 + 4];
#pragma unroll
                    for (int i = 0; i < 4; i++) {
                        unsigned long long pi = pk2(p4[i][t], p4[i][t]);
                        fma2(o2[i][0], pi, v0.x);
                        fma2(o2[i][1], pi, v0.y);
                        fma2(o2[i][2], pi, v1.x);
                        fma2(o2[i][3], pi, v1.y);
                    }
                }
            }
        }
        __syncthreads();   // E: P/Vs free for next tile
    }

    // finalize: divide by l, store
#pragma unroll
    for (int i = 0; i < 4; i++) {
        float inv = 1.f / sm.row_l[ty * 4 + i];
        float* orow = out + (size_t)b * T * H
                    + (size_t)(qt * QT + ty * 4 + i) * H + tx * 8;
        float2 p0 = up2(o2[i][0]), p1 = up2(o2[i][1]);
        float2 p2 = up2(o2[i][2]), p3 = up2(o2[i][3]);
        *(float4*)(orow)     = make_float4(p0.x * inv, p0.y * inv, p1.x * inv, p1.y * inv);
        *(float4*)(orow + 4) = make_float4(p2.x * inv, p2.y * inv, p3.x * inv, p3.y * inv);
    }
}

// ============================================================
extern "C" void kernel_launch(void* const* d_in, const int* in_sizes, int n_in,
                              void* d_out, int out_size)
{
    const float* x  = (const float*)d_in[0];
    const float* Wk = (const float*)d_in[1];
    const float* Wq = (const float*)d_in[2];
    const float* Wv = (const float*)d_in[3];
    float* out = (float*)d_out;

    cudaFuncSetAttribute(attn_kernel,
                         cudaFuncAttributeMaxDynamicSharedMemorySize,
                         (int)sizeof(AttnSmem));

    proj_kernel<<<dim3(3, NROWS / 128), 256>>>(x, Wk, Wq, Wv);
    attn_kernel<<<dim3(256, 1), 256, sizeof(AttnSmem)>>>(out);
    (void)in_sizes; (void)n_in; (void)out_size;
}

// round 6
// speedup vs baseline: 1.7197x; 1.5826x over previous
#include <cuda_runtime.h>
#include <cuda_fp16.h>
#include <math_constants.h>
#include <cstdint>

#define Bsz 8
#define T   2048
#define C   1024
#define H   128
#define NROWS (Bsz * T)

// -------- gmem scratch (halves only; no fp32 round-trip) --------
__device__ __half g_qh[NROWS * H];
__device__ __half g_ql[NROWS * H];
__device__ __half g_kh[NROWS * H];
__device__ __half g_kl[NROWS * H];
__device__ __half g_vth[Bsz * H * T];   // V^T hi: [b][h][t]
__device__ __half g_vtl[Bsz * H * T];   // V^T lo

// -------- helpers --------
__device__ __forceinline__ void mma16816(float* c, const unsigned* a, const unsigned* b) {
    asm volatile(
        "mma.sync.aligned.m16n8k16.row.col.f32.f16.f16.f32 "
        "{%0,%1,%2,%3}, {%4,%5,%6,%7}, {%8,%9}, {%0,%1,%2,%3};"
        : "+f"(c[0]), "+f"(c[1]), "+f"(c[2]), "+f"(c[3])
        : "r"(a[0]), "r"(a[1]), "r"(a[2]), "r"(a[3]), "r"(b[0]), "r"(b[1]));
}
__device__ __forceinline__ unsigned h2u(float x, float y) {
    __half2 h = __floats2half2_rn(x, y);
    return *reinterpret_cast<unsigned*>(&h);
}
// residual pair: lo = round((x,y) - half(x,y))
__device__ __forceinline__ unsigned h2lo(float x, float y, unsigned hi) {
    __half2 h = *reinterpret_cast<__half2*>(&hi);
    float2 f = __half22float2(h);
    __half2 l = __floats2half2_rn(x - f.x, y - f.y);
    return *reinterpret_cast<unsigned*>(&l);
}

// ============================================================
// Projection GEMM (HMMA fp16x3): out = x[16384,1024] @ W[1024,128]
// blockIdx.x: 0=K, 1=Q(x32), 2=V(transposed). Fused split epilogue.
// BM=128, BN=128, BK=32. 8 warps: warp_m=w&3 (32 rows), warp_n=w>>2 (64 cols).
// ============================================================
#define PSTR 40   // half stride (80B): conflict-free for 8-row frag reads

__global__ __launch_bounds__(256) void proj_kernel(
    const float* __restrict__ x,
    const float* __restrict__ Wk,
    const float* __restrict__ Wq,
    const float* __restrict__ Wv)
{
    __shared__ __half Ah[128][PSTR], Al[128][PSTR];   // x tile [m][k]
    __shared__ __half Bh[128][PSTR], Bl[128][PSTR];   // W tile transposed [n][k]

    const int sel = blockIdx.x;
    const float* W = (sel == 0) ? Wk : (sel == 1) ? Wq : Wv;
    const int m0 = blockIdx.y * 128;

    const int tid = threadIdx.x;
    const int w = tid >> 5, lane = tid & 31;
    const int wm = w & 3, wn = w >> 2;
    const int g = lane >> 2, t = lane & 3;

    float c[2][8][4];
#pragma unroll
    for (int mt = 0; mt < 2; mt++)
#pragma unroll
        for (int j = 0; j < 8; j++)
#pragma unroll
            for (int e = 0; e < 4; e++) c[mt][j][e] = 0.f;

    for (int k0 = 0; k0 < C; k0 += 32) {
        // x tile: 128x32 floats -> split halves
#pragma unroll
        for (int i = 0; i < 4; i++) {
            int idx = tid + i * 256;
            int row = idx >> 3, c4 = (idx & 7) * 4;
            float4 v = *(const float4*)(x + (size_t)(m0 + row) * C + k0 + c4);
            unsigned h0 = h2u(v.x, v.y), h1 = h2u(v.z, v.w);
            *(unsigned*)&Ah[row][c4]     = h0;
            *(unsigned*)&Ah[row][c4 + 2] = h1;
            *(unsigned*)&Al[row][c4]     = h2lo(v.x, v.y, h0);
            *(unsigned*)&Al[row][c4 + 2] = h2lo(v.z, v.w, h1);
        }
        // W tile: 32x128 -> transposed split halves Bh[n][k]
#pragma unroll
        for (int i = 0; i < 4; i++) {
            int idx = tid + i * 256;
            int k = idx >> 5, n4 = (idx & 31) * 4;
            float4 v = *(const float4*)(W + (size_t)(k0 + k) * H + n4);
            float vv[4] = {v.x, v.y, v.z, v.w};
#pragma unroll
            for (int e = 0; e < 4; e++) {
                __half h = __float2half_rn(vv[e]);
                Bh[n4 + e][k] = h;
                Bl[n4 + e][k] = __float2half_rn(vv[e] - __half2float(h));
            }
        }
        __syncthreads();

#pragma unroll
        for (int kk = 0; kk < 2; kk++) {
            const int col0 = kk * 16 + 2 * t;
            unsigned ah[2][4], al[2][4];
#pragma unroll
            for (int mt = 0; mt < 2; mt++) {
                int row = wm * 32 + mt * 16 + g;
                ah[mt][0] = *(unsigned*)&Ah[row][col0];
                ah[mt][1] = *(unsigned*)&Ah[row + 8][col0];
                ah[mt][2] = *(unsigned*)&Ah[row][col0 + 8];
                ah[mt][3] = *(unsigned*)&Ah[row + 8][col0 + 8];
                al[mt][0] = *(unsigned*)&Al[row][col0];
                al[mt][1] = *(unsigned*)&Al[row + 8][col0];
                al[mt][2] = *(unsigned*)&Al[row][col0 + 8];
                al[mt][3] = *(unsigned*)&Al[row + 8][col0 + 8];
            }
#pragma unroll
            for (int j = 0; j < 8; j++) {
                int n = wn * 64 + j * 8 + g;
                unsigned bh[2] = { *(unsigned*)&Bh[n][col0], *(unsigned*)&Bh[n][col0 + 8] };
                unsigned bl[2] = { *(unsigned*)&Bl[n][col0], *(unsigned*)&Bl[n][col0 + 8] };
#pragma unroll
                for (int mt = 0; mt < 2; mt++) {
                    mma16816(c[mt][j], ah[mt], bh);
                    mma16816(c[mt][j], ah[mt], bl);
                    mma16816(c[mt][j], al[mt], bh);
                }
            }
        }
        __syncthreads();
    }

    // ---- fused split epilogue
    if (sel == 2) {
        // V: transposed hi/lo halves  vt[b][h][t]
#pragma unroll
        for (int mt = 0; mt < 2; mt++)
#pragma unroll
            for (int j = 0; j < 8; j++) {
                int row0 = m0 + wm * 32 + mt * 16 + g;
                int col = wn * 64 + j * 8 + 2 * t;
#pragma unroll
                for (int e = 0; e < 4; e++) {
                    int row = row0 + (e >> 1) * 8;
                    int n = col + (e & 1);
                    float val = c[mt][j][e];
                    __half h = __float2half_rn(val);
                    size_t a = ((size_t)(row >> 11) * H + n) * T + (row & 2047);
                    g_vth[a] = h;
                    g_vtl[a] = __float2half_rn(val - __half2float(h));
                }
            }
    } else {
        __half* ghi = (sel == 0) ? g_kh : g_qh;
        __half* glo = (sel == 0) ? g_kl : g_ql;
        const float sc = (sel == 1) ? 32.f : 1.f;   // fold C**0.5 into Q (exact pow2)
#pragma unroll
        for (int mt = 0; mt < 2; mt++)
#pragma unroll
            for (int j = 0; j < 8; j++) {
                int row0 = m0 + wm * 32 + mt * 16 + g;
                int col = wn * 64 + j * 8 + 2 * t;
#pragma unroll
                for (int half_row = 0; half_row < 2; half_row++) {
                    int row = row0 + half_row * 8;
                    float v0 = c[mt][j][half_row * 2] * sc;
                    float v1 = c[mt][j][half_row * 2 + 1] * sc;
                    unsigned hi = h2u(v0, v1);
                    unsigned lo = h2lo(v0, v1, hi);
                    *(unsigned*)(ghi + (size_t)row * H + col) = hi;
                    *(unsigned*)(glo + (size_t)row * H + col) = lo;
                }
            }
    }
}

// ============================================================
// Flash attention (HMMA fp16x3), causal. Q tile 64, KV tile 64.
// 8 warps: warp_m = w&3 (16 q rows), warp_n = w>>2 (32 kv cols).
// S/P/O in registers; cross-half softmax via pmax/psum smem;
// partial O combined across warp_n at the end.
// 256 CTAs, LPT (longest q-tiles first).
// ============================================================
#define ASTR 136   // half stride (272B)
#define VSTR 72    // half stride (144B)

#define OFF_QH   0
#define OFF_QL   17408
#define OFF_KH   34816
#define OFF_KL   52224
#define OFF_VTH  69632
#define OFF_VTL  88064
#define OFF_PMAX 106496
#define OFF_PSUM 107008
#define SMEM_ATTN 107520

__global__ __launch_bounds__(256, 1) void attn_kernel(float* __restrict__ out)
{
    extern __shared__ char smem[];
    __half (*QH)[ASTR]  = (__half(*)[ASTR])(smem + OFF_QH);
    __half (*QL)[ASTR]  = (__half(*)[ASTR])(smem + OFF_QL);
    __half (*KH)[ASTR]  = (__half(*)[ASTR])(smem + OFF_KH);
    __half (*KL)[ASTR]  = (__half(*)[ASTR])(smem + OFF_KL);
    __half (*VTH)[VSTR] = (__half(*)[VSTR])(smem + OFF_VTH);
    __half (*VTL)[VSTR] = (__half(*)[VSTR])(smem + OFF_VTL);
    float (*pmax)[64] = (float(*)[64])(smem + OFF_PMAX);
    float (*psum)[64] = (float(*)[64])(smem + OFF_PSUM);

    const int tid = threadIdx.x;
    const int w = tid >> 5, lane = tid & 31;
    const int wm = w & 3, wn = w >> 2;
    const int g = lane >> 2, t = lane & 3;
    const int bx = blockIdx.x;
    const int b = bx & 7;
    const int qt = 31 - (bx >> 3);          // LPT: heavy first

    const __half* QHg = g_qh + ((size_t)b * T + (size_t)qt * 64) * H;
    const __half* QLg = g_ql + ((size_t)b * T + (size_t)qt * 64) * H;
    const __half* KHg = g_kh + (size_t)b * T * H;
    const __half* KLg = g_kl + (size_t)b * T * H;
    const __half* VHg = g_vth + (size_t)b * H * T;
    const __half* VLg = g_vtl + (size_t)b * H * T;

    // Q tiles: 64x128 halves each
#pragma unroll
    for (int i = 0; i < 4; i++) {
        int idx = tid + i * 256;
        int row = idx >> 4, c8 = (idx & 15) * 8;
        *(uint4*)&QH[row][c8] = *(const uint4*)(QHg + (size_t)row * H + c8);
        *(uint4*)&QL[row][c8] = *(const uint4*)(QLg + (size_t)row * H + c8);
    }

    const int r0 = wm * 16 + g, r1 = r0 + 8;
    float m[2] = {-1e30f, -1e30f}, l[2] = {0.f, 0.f};
    float o[16][4];
#pragma unroll
    for (int j = 0; j < 16; j++)
#pragma unroll
        for (int e = 0; e < 4; e++) o[j][e] = 0.f;

    for (int kt = 0; kt <= qt; kt++) {
        __syncthreads();   // protect prev-tile K/V reads (and orders Q on iter 0)
#pragma unroll
        for (int i = 0; i < 4; i++) {
            int idx = tid + i * 256;
            int row = idx >> 4, c8 = (idx & 15) * 8;
            *(uint4*)&KH[row][c8] = *(const uint4*)(KHg + ((size_t)kt * 64 + row) * H + c8);
            *(uint4*)&KL[row][c8] = *(const uint4*)(KLg + ((size_t)kt * 64 + row) * H + c8);
            int vr = idx >> 3, v8 = (idx & 7) * 8;
            *(uint4*)&VTH[vr][v8] = *(const uint4*)(VHg + (size_t)vr * T + kt * 64 + v8);
            *(uint4*)&VTL[vr][v8] = *(const uint4*)(VLg + (size_t)vr * T + kt * 64 + v8);
        }
        __syncthreads();

        // ---- S = Q K^T (3-pass split), warp computes 16x32
        float s[4][4];
#pragma unroll
        for (int j = 0; j < 4; j++)
#pragma unroll
            for (int e = 0; e < 4; e++) s[j][e] = 0.f;

#pragma unroll
        for (int kk = 0; kk < 8; kk++) {
            const int col0 = kk * 16 + 2 * t;
            unsigned ah[4], al[4];
            ah[0] = *(unsigned*)&QH[r0][col0];
            ah[1] = *(unsigned*)&QH[r1][col0];
            ah[2] = *(unsigned*)&QH[r0][col0 + 8];
            ah[3] = *(unsigned*)&QH[r1][col0 + 8];
            al[0] = *(unsigned*)&QL[r0][col0];
            al[1] = *(unsigned*)&QL[r1][col0];
            al[2] = *(unsigned*)&QL[r0][col0 + 8];
            al[3] = *(unsigned*)&QL[r1][col0 + 8];
#pragma unroll
            for (int j = 0; j < 4; j++) {
                int n = wn * 32 + j * 8 + g;
                unsigned bh[2] = { *(unsigned*)&KH[n][col0], *(unsigned*)&KH[n][col0 + 8] };
                unsigned bl[2] = { *(unsigned*)&KL[n][col0], *(unsigned*)&KL[n][col0 + 8] };
                mma16816(s[j], ah, bh);
                mma16816(s[j], ah, bl);
                mma16816(s[j], al, bh);
            }
        }

        // ---- causal mask (only the diagonal tile)
        if (kt == qt) {
#pragma unroll
            for (int j = 0; j < 4; j++) {
                int cl = wn * 32 + j * 8 + 2 * t;
                if (cl     > r0) s[j][0] = -3e38f;
                if (cl + 1 > r0) s[j][1] = -3e38f;
                if (cl     > r1) s[j][2] = -3e38f;
                if (cl + 1 > r1) s[j][3] = -3e38f;
            }
        }

        // ---- online softmax (cross-half via smem)
        float mx0 = -3e38f, mx1 = -3e38f;
#pragma unroll
        for (int j = 0; j < 4; j++) {
            mx0 = fmaxf(mx0, fmaxf(s[j][0], s[j][1]));
            mx1 = fmaxf(mx1, fmaxf(s[j][2], s[j][3]));
        }
        mx0 = fmaxf(mx0, __shfl_xor_sync(0xFFFFFFFFu, mx0, 1));
        mx0 = fmaxf(mx0, __shfl_xor_sync(0xFFFFFFFFu, mx0, 2));
        mx1 = fmaxf(mx1, __shfl_xor_sync(0xFFFFFFFFu, mx1, 1));
        mx1 = fmaxf(mx1, __shfl_xor_sync(0xFFFFFFFFu, mx1, 2));
        if (t == 0) { pmax[wn][r0] = mx0; pmax[wn][r1] = mx1; }
        __syncthreads();

        float mn0 = fmaxf(m[0], fmaxf(pmax[0][r0], pmax[1][r0]));
        float mn1 = fmaxf(m[1], fmaxf(pmax[0][r1], pmax[1][r1]));
        float al0 = __expf(m[0] - mn0);
        float al1 = __expf(m[1] - mn1);

        float sum0 = 0.f, sum1 = 0.f;
#pragma unroll
        for (int j = 0; j < 4; j++) {
            s[j][0] = __expf(s[j][0] - mn0);
            s[j][1] = __expf(s[j][1] - mn0);
            s[j][2] = __expf(s[j][2] - mn1);
            s[j][3] = __expf(s[j][3] - mn1);
            sum0 += s[j][0] + s[j][1];
            sum1 += s[j][2] + s[j][3];
        }
        sum0 += __shfl_xor_sync(0xFFFFFFFFu, sum0, 1);
        sum0 += __shfl_xor_sync(0xFFFFFFFFu, sum0, 2);
        sum1 += __shfl_xor_sync(0xFFFFFFFFu, sum1, 1);
        sum1 += __shfl_xor_sync(0xFFFFFFFFu, sum1, 2);
        if (t == 0) { psum[wn][r0] = sum0; psum[wn][r1] = sum1; }
        __syncthreads();

        l[0] = l[0] * al0 + psum[0][r0] + psum[1][r0];
        l[1] = l[1] * al1 + psum[0][r1] + psum[1][r1];
        m[0] = mn0; m[1] = mn1;

        // ---- rescale O, then O += P V (3-pass split; partial over this half's keys)
#pragma unroll
        for (int j = 0; j < 16; j++) {
            o[j][0] *= al0; o[j][1] *= al0;
            o[j][2] *= al1; o[j][3] *= al1;
        }
#pragma unroll
        for (int kk2 = 0; kk2 < 2; kk2++) {
            unsigned aph[4], apl[4];
            aph[0] = h2u(s[2*kk2][0], s[2*kk2][1]);
            aph[1] = h2u(s[2*kk2][2], s[2*kk2][3]);
            aph[2] = h2u(s[2*kk2+1][0], s[2*kk2+1][1]);
            aph[3] = h2u(s[2*kk2+1][2], s[2*kk2+1][3]);
            apl[0] = h2lo(s[2*kk2][0], s[2*kk2][1], aph[0]);
            apl[1] = h2lo(s[2*kk2][2], s[2*kk2][3], aph[1]);
            apl[2] = h2lo(s[2*kk2+1][0], s[2*kk2+1][1], aph[2]);
            apl[3] = h2lo(s[2*kk2+1][2], s[2*kk2+1][3], aph[3]);
            const int col = wn * 32 + kk2 * 16 + 2 * t;
#pragma unroll
            for (int j2 = 0; j2 < 16; j2++) {
                int h = j2 * 8 + g;
                unsigned bh[2] = { *(unsigned*)&VTH[h][col], *(unsigned*)&VTH[h][col + 8] };
                unsigned bl[2] = { *(unsigned*)&VTL[h][col], *(unsigned*)&VTL[h][col + 8] };
                mma16816(o[j2], aph, bh);
                mma16816(o[j2], aph, bl);
                mma16816(o[j2], apl, bh);
            }
        }
    }

    // ---- combine the two warp_n partial O's, normalize, store
    float (*Ocomb)[132] = (float(*)[132])(smem + OFF_QH);   // overlay dead Q area
    __syncthreads();
    if (wn == 1) {
#pragma unroll
        for (int j2 = 0; j2 < 16; j2++) {
            int col = j2 * 8 + 2 * t;
            *(float2*)&Ocomb[r0][col] = make_float2(o[j2][0], o[j2][1]);
            *(float2*)&Ocomb[r1][col] = make_float2(o[j2][2], o[j2][3]);
        }
    }
    __syncthreads();
    if (wn == 0) {
        const float inv0 = 1.f / l[0], inv1 = 1.f / l[1];
        float* out0 = out + ((size_t)b * T + (size_t)qt * 64 + r0) * H;
        float* out1 = out + ((size_t)b * T + (size_t)qt * 64 + r1) * H;
#pragma unroll
        for (int j2 = 0; j2 < 16; j2++) {
            int col = j2 * 8 + 2 * t;
            *(float2*)(out0 + col) = make_float2((o[j2][0] + Ocomb[r0][col])     * inv0,
                                                 (o[j2][1] + Ocomb[r0][col + 1]) * inv0);
            *(float2*)(out1 + col) = make_float2((o[j2][2] + Ocomb[r1][col])     * inv1,
                                                 (o[j2][3] + Ocomb[r1][col + 1]) * inv1);
        }
    }
}

// ============================================================
extern "C" void kernel_launch(void* const* d_in, const int* in_sizes, int n_in,
                              void* d_out, int out_size)
{
    const float* x  = (const float*)d_in[0];
    const float* Wk = (const float*)d_in[1];
    const float* Wq = (const float*)d_in[2];
    const float* Wv = (const float*)d_in[3];
    float* out = (float*)d_out;

    cudaFuncSetAttribute(attn_kernel,
                         cudaFuncAttributeMaxDynamicSharedMemorySize, SMEM_ATTN);

    proj_kernel<<<dim3(3, NROWS / 128), 256>>>(x, Wk, Wq, Wv);
    attn_kernel<<<256, 256, SMEM_ATTN>>>(out);
    (void)in_sizes; (void)n_in; (void)out_size;
}

// round 7
// speedup vs baseline: 2.9393x; 1.7092x over previous
#include <cuda_runtime.h>
#include <cuda_fp16.h>
#include <math_constants.h>
#include <cstdint>

#define Bsz 8
#define T   2048
#define C   1024
#define H   128
#define NROWS (Bsz * T)

// -------- gmem scratch (16B aligned for uint4 access) --------
__device__ __align__(16) __half g_xh[NROWS * C];
__device__ __align__(16) __half g_xl[NROWS * C];
__device__ __align__(16) __half g_wth[3 * H * C];   // W^T hi: [sel][n][k]
__device__ __align__(16) __half g_wtl[3 * H * C];   // W^T lo
__device__ __align__(16) __half g_qh[NROWS * H];
__device__ __align__(16) __half g_ql[NROWS * H];
__device__ __align__(16) __half g_kh[NROWS * H];
__device__ __align__(16) __half g_kl[NROWS * H];
__device__ __align__(16) __half g_vth[Bsz * H * T];   // V^T hi: [b][h][t]
__device__ __align__(16) __half g_vtl[Bsz * H * T];   // V^T lo

// -------- helpers --------
__device__ __forceinline__ void mma16816(float* c, const unsigned* a, const unsigned* b) {
    asm volatile(
        "mma.sync.aligned.m16n8k16.row.col.f32.f16.f16.f32 "
        "{%0,%1,%2,%3}, {%4,%5,%6,%7}, {%8,%9}, {%0,%1,%2,%3};"
        : "+f"(c[0]), "+f"(c[1]), "+f"(c[2]), "+f"(c[3])
        : "r"(a[0]), "r"(a[1]), "r"(a[2]), "r"(a[3]), "r"(b[0]), "r"(b[1]));
}
__device__ __forceinline__ unsigned h2u(float x, float y) {
    __half2 h = __floats2half2_rn(x, y);
    return *reinterpret_cast<unsigned*>(&h);
}
__device__ __forceinline__ unsigned h2lo(float x, float y, unsigned hi) {
    __half2 h = *reinterpret_cast<__half2*>(&hi);
    float2 f = __half22float2(h);
    __half2 l = __floats2half2_rn(x - f.x, y - f.y);
    return *reinterpret_cast<unsigned*>(&l);
}

// ============================================================
// split_kernel: x (fp32) -> g_xh/g_xl (fp16 hi/lo), coalesced.
// 4096 blocks x 256 threads, 4 float4 per thread.
// ============================================================
__global__ __launch_bounds__(256) void split_kernel(const float* __restrict__ x)
{
    const int tid = threadIdx.x;
#pragma unroll
    for (int i = 0; i < 4; i++) {
        unsigned u = blockIdx.x * 1024 + i * 256 + tid;   // float4 index
        float4 v = ((const float4*)x)[u];
        unsigned h0 = h2u(v.x, v.y), h1 = h2u(v.z, v.w);
        unsigned l0 = h2lo(v.x, v.y, h0), l1 = h2lo(v.z, v.w, h1);
        ((uint2*)g_xh)[u] = make_uint2(h0, h1);
        ((uint2*)g_xl)[u] = make_uint2(l0, l1);
    }
}

// ============================================================
// wsplit_kernel: W[k][n] -> W^T hi/lo [sel][n][k]. Grid (3, 32).
// Each block: 32 k-rows x 128 n, smem transpose.
// ============================================================
__global__ __launch_bounds__(256) void wsplit_kernel(
    const float* __restrict__ Wk, const float* __restrict__ Wq,
    const float* __restrict__ Wv)
{
    __shared__ float ws[32][133];
    const int sel = blockIdx.x;
    const float* W = (sel == 0) ? Wk : (sel == 1) ? Wq : Wv;
    const int k0 = blockIdx.y * 32;
    const int tid = threadIdx.x;
#pragma unroll
    for (int i = 0; i < 16; i++) {
        int idx = tid + i * 256;
        int k = idx >> 7, n = idx & 127;
        ws[k][n] = W[(size_t)(k0 + k) * H + n];
    }
    __syncthreads();
    __half* wth = g_wth + (size_t)sel * H * C;
    __half* wtl = g_wtl + (size_t)sel * H * C;
#pragma unroll
    for (int i = 0; i < 16; i++) {
        int idx = tid + i * 256;
        int n = idx >> 5, kk = idx & 31;
        float v = ws[kk][n];
        __half h = __float2half_rn(v);
        wth[(size_t)n * C + k0 + kk] = h;
        wtl[(size_t)n * C + k0 + kk] = __float2half_rn(v - __half2float(h));
    }
}

// ============================================================
// Projection GEMM (HMMA fp16x3): out = x @ W, pre-split half inputs.
// blockIdx.x: 0=K, 1=Q(x32), 2=V(transposed). Fused split epilogue.
// BM=128, BN=128, BK=32. 8 warps; 2 CTAs/SM.
// ============================================================
#define PSTR 40

__global__ __launch_bounds__(256, 2) void proj_kernel()
{
    __shared__ __half Ah[128][PSTR], Al[128][PSTR];   // x tile [m][k]
    __shared__ __half Bh[128][PSTR], Bl[128][PSTR];   // W^T tile [n][k]

    const int sel = blockIdx.x;
    const int m0 = blockIdx.y * 128;

    const int tid = threadIdx.x;
    const int w = tid >> 5, lane = tid & 31;
    const int wm = w & 3, wn = w >> 2;
    const int g = lane >> 2, t = lane & 3;

    const __half* xh = g_xh + (size_t)m0 * C;
    const __half* xl = g_xl + (size_t)m0 * C;
    const __half* wth = g_wth + (size_t)sel * H * C;
    const __half* wtl = g_wtl + (size_t)sel * H * C;

    float c[2][8][4];
#pragma unroll
    for (int mt = 0; mt < 2; mt++)
#pragma unroll
        for (int j = 0; j < 8; j++)
#pragma unroll
            for (int e = 0; e < 4; e++) c[mt][j][e] = 0.f;

    for (int k0 = 0; k0 < C; k0 += 32) {
        // 128 rows x 32 halves per array: 512 uint4, 2 per thread per array
#pragma unroll
        for (int i = 0; i < 2; i++) {
            int idx = tid + i * 256;
            int row = idx >> 2, c8 = (idx & 3) * 8;
            *(uint4*)&Ah[row][c8] = *(const uint4*)(xh + (size_t)row * C + k0 + c8);
            *(uint4*)&Al[row][c8] = *(const uint4*)(xl + (size_t)row * C + k0 + c8);
            *(uint4*)&Bh[row][c8] = *(const uint4*)(wth + (size_t)row * C + k0 + c8);
            *(uint4*)&Bl[row][c8] = *(const uint4*)(wtl + (size_t)row * C + k0 + c8);
        }
        __syncthreads();

#pragma unroll
        for (int kk = 0; kk < 2; kk++) {
            const int col0 = kk * 16 + 2 * t;
            unsigned ah[2][4], al[2][4];
#pragma unroll
            for (int mt = 0; mt < 2; mt++) {
                int row = wm * 32 + mt * 16 + g;
                ah[mt][0] = *(unsigned*)&Ah[row][col0];
                ah[mt][1] = *(unsigned*)&Ah[row + 8][col0];
                ah[mt][2] = *(unsigned*)&Ah[row][col0 + 8];
                ah[mt][3] = *(unsigned*)&Ah[row + 8][col0 + 8];
                al[mt][0] = *(unsigned*)&Al[row][col0];
                al[mt][1] = *(unsigned*)&Al[row + 8][col0];
                al[mt][2] = *(unsigned*)&Al[row][col0 + 8];
                al[mt][3] = *(unsigned*)&Al[row + 8][col0 + 8];
            }
#pragma unroll
            for (int j = 0; j < 8; j++) {
                int n = wn * 64 + j * 8 + g;
                unsigned bh[2] = { *(unsigned*)&Bh[n][col0], *(unsigned*)&Bh[n][col0 + 8] };
                unsigned bl[2] = { *(unsigned*)&Bl[n][col0], *(unsigned*)&Bl[n][col0 + 8] };
#pragma unroll
                for (int mt = 0; mt < 2; mt++) {
                    mma16816(c[mt][j], ah[mt], bh);
                    mma16816(c[mt][j], ah[mt], bl);
                    mma16816(c[mt][j], al[mt], bh);
                }
            }
        }
        __syncthreads();
    }

    // ---- fused split epilogue
    if (sel == 2) {
#pragma unroll
        for (int mt = 0; mt < 2; mt++)
#pragma unroll
            for (int j = 0; j < 8; j++) {
                int row0 = m0 + wm * 32 + mt * 16 + g;
                int col = wn * 64 + j * 8 + 2 * t;
#pragma unroll
                for (int e = 0; e < 4; e++) {
                    int row = row0 + (e >> 1) * 8;
                    int n = col + (e & 1);
                    float val = c[mt][j][e];
                    __half h = __float2half_rn(val);
                    size_t a = ((size_t)(row >> 11) * H + n) * T + (row & 2047);
                    g_vth[a] = h;
                    g_vtl[a] = __float2half_rn(val - __half2float(h));
                }
            }
    } else {
        __half* ghi = (sel == 0) ? g_kh : g_qh;
        __half* glo = (sel == 0) ? g_kl : g_ql;
        const float sc = (sel == 1) ? 32.f : 1.f;
#pragma unroll
        for (int mt = 0; mt < 2; mt++)
#pragma unroll
            for (int j = 0; j < 8; j++) {
                int row0 = m0 + wm * 32 + mt * 16 + g;
                int col = wn * 64 + j * 8 + 2 * t;
#pragma unroll
                for (int half_row = 0; half_row < 2; half_row++) {
                    int row = row0 + half_row * 8;
                    float v0 = c[mt][j][half_row * 2] * sc;
                    float v1 = c[mt][j][half_row * 2 + 1] * sc;
                    unsigned hi = h2u(v0, v1);
                    unsigned lo = h2lo(v0, v1, hi);
                    *(unsigned*)(ghi + (size_t)row * H + col) = hi;
                    *(unsigned*)(glo + (size_t)row * H + col) = lo;
                }
            }
    }
}

// ============================================================
// Flash attention (HMMA fp16x3), causal — unchanged from R6.
// ============================================================
#define ASTR 136
#define VSTR 72

#define OFF_QH   0
#define OFF_QL   17408
#define OFF_KH   34816
#define OFF_KL   52224
#define OFF_VTH  69632
#define OFF_VTL  88064
#define OFF_PMAX 106496
#define OFF_PSUM 107008
#define SMEM_ATTN 107520

__global__ __launch_bounds__(256, 1) void attn_kernel(float* __restrict__ out)
{
    extern __shared__ char smem[];
    __half (*QH)[ASTR]  = (__half(*)[ASTR])(smem + OFF_QH);
    __half (*QL)[ASTR]  = (__half(*)[ASTR])(smem + OFF_QL);
    __half (*KH)[ASTR]  = (__half(*)[ASTR])(smem + OFF_KH);
    __half (*KL)[ASTR]  = (__half(*)[ASTR])(smem + OFF_KL);
    __half (*VTH)[VSTR] = (__half(*)[VSTR])(smem + OFF_VTH);
    __half (*VTL)[VSTR] = (__half(*)[VSTR])(smem + OFF_VTL);
    float (*pmax)[64] = (float(*)[64])(smem + OFF_PMAX);
    float (*psum)[64] = (float(*)[64])(smem + OFF_PSUM);

    const int tid = threadIdx.x;
    const int w = tid >> 5, lane = tid & 31;
    const int wm = w & 3, wn = w >> 2;
    const int g = lane >> 2, t = lane & 3;
    const int bx = blockIdx.x;
    const int b = bx & 7;
    const int qt = 31 - (bx >> 3);

    const __half* QHg = g_qh + ((size_t)b * T + (size_t)qt * 64) * H;
    const __half* QLg = g_ql + ((size_t)b * T + (size_t)qt * 64) * H;
    const __half* KHg = g_kh + (size_t)b * T * H;
    const __half* KLg = g_kl + (size_t)b * T * H;
    const __half* VHg = g_vth + (size_t)b * H * T;
    const __half* VLg = g_vtl + (size_t)b * H * T;

#pragma unroll
    for (int i = 0; i < 4; i++) {
        int idx = tid + i * 256;
        int row = idx >> 4, c8 = (idx & 15) * 8;
        *(uint4*)&QH[row][c8] = *(const uint4*)(QHg + (size_t)row * H + c8);
        *(uint4*)&QL[row][c8] = *(const uint4*)(QLg + (size_t)row * H + c8);
    }

    const int r0 = wm * 16 + g, r1 = r0 + 8;
    float m[2] = {-1e30f, -1e30f}, l[2] = {0.f, 0.f};
    float o[16][4];
#pragma unroll
    for (int j = 0; j < 16; j++)
#pragma unroll
        for (int e = 0; e < 4; e++) o[j][e] = 0.f;

    for (int kt = 0; kt <= qt; kt++) {
        __syncthreads();
#pragma unroll
        for (int i = 0; i < 4; i++) {
            int idx = tid + i * 256;
            int row = idx >> 4, c8 = (idx & 15) * 8;
            *(uint4*)&KH[row][c8] = *(const uint4*)(KHg + ((size_t)kt * 64 + row) * H + c8);
            *(uint4*)&KL[row][c8] = *(const uint4*)(KLg + ((size_t)kt * 64 + row) * H + c8);
            int vr = idx >> 3, v8 = (idx & 7) * 8;
            *(uint4*)&VTH[vr][v8] = *(const uint4*)(VHg + (size_t)vr * T + kt * 64 + v8);
            *(uint4*)&VTL[vr][v8] = *(const uint4*)(VLg + (size_t)vr * T + kt * 64 + v8);
        }
        __syncthreads();

        float s[4][4];
#pragma unroll
        for (int j = 0; j < 4; j++)
#pragma unroll
            for (int e = 0; e < 4; e++) s[j][e] = 0.f;

#pragma unroll
        for (int kk = 0; kk < 8; kk++) {
            const int col0 = kk * 16 + 2 * t;
            unsigned ah[4], al[4];
            ah[0] = *(unsigned*)&QH[r0][col0];
            ah[1] = *(unsigned*)&QH[r1][col0];
            ah[2] = *(unsigned*)&QH[r0][col0 + 8];
            ah[3] = *(unsigned*)&QH[r1][col0 + 8];
            al[0] = *(unsigned*)&QL[r0][col0];
            al[1] = *(unsigned*)&QL[r1][col0];
            al[2] = *(unsigned*)&QL[r0][col0 + 8];
            al[3] = *(unsigned*)&QL[r1][col0 + 8];
#pragma unroll
            for (int j = 0; j < 4; j++) {
                int n = wn * 32 + j * 8 + g;
                unsigned bh[2] = { *(unsigned*)&KH[n][col0], *(unsigned*)&KH[n][col0 + 8] };
                unsigned bl[2] = { *(unsigned*)&KL[n][col0], *(unsigned*)&KL[n][col0 + 8] };
                mma16816(s[j], ah, bh);
                mma16816(s[j], ah, bl);
                mma16816(s[j], al, bh);
            }
        }

        if (kt == qt) {
#pragma unroll
            for (int j = 0; j < 4; j++) {
                int cl = wn * 32 + j * 8 + 2 * t;
                if (cl     > r0) s[j][0] = -3e38f;
                if (cl + 1 > r0) s[j][1] = -3e38f;
                if (cl     > r1) s[j][2] = -3e38f;
                if (cl + 1 > r1) s[j][3] = -3e38f;
            }
        }

        float mx0 = -3e38f, mx1 = -3e38f;
#pragma unroll
        for (int j = 0; j < 4; j++) {
            mx0 = fmaxf(mx0, fmaxf(s[j][0], s[j][1]));
            mx1 = fmaxf(mx1, fmaxf(s[j][2], s[j][3]));
        }
        mx0 = fmaxf(mx0, __shfl_xor_sync(0xFFFFFFFFu, mx0, 1));
        mx0 = fmaxf(mx0, __shfl_xor_sync(0xFFFFFFFFu, mx0, 2));
        mx1 = fmaxf(mx1, __shfl_xor_sync(0xFFFFFFFFu, mx1, 1));
        mx1 = fmaxf(mx1, __shfl_xor_sync(0xFFFFFFFFu, mx1, 2));
        if (t == 0) { pmax[wn][r0] = mx0; pmax[wn][r1] = mx1; }
        __syncthreads();

        float mn0 = fmaxf(m[0], fmaxf(pmax[0][r0], pmax[1][r0]));
        float mn1 = fmaxf(m[1], fmaxf(pmax[0][r1], pmax[1][r1]));
        float al0 = __expf(m[0] - mn0);
        float al1 = __expf(m[1] - mn1);

        float sum0 = 0.f, sum1 = 0.f;
#pragma unroll
        for (int j = 0; j < 4; j++) {
            s[j][0] = __expf(s[j][0] - mn0);
            s[j][1] = __expf(s[j][1] - mn0);
            s[j][2] = __expf(s[j][2] - mn1);
            s[j][3] = __expf(s[j][3] - mn1);
            sum0 += s[j][0] + s[j][1];
            sum1 += s[j][2] + s[j][3];
        }
        sum0 += __shfl_xor_sync(0xFFFFFFFFu, sum0, 1);
        sum0 += __shfl_xor_sync(0xFFFFFFFFu, sum0, 2);
        sum1 += __shfl_xor_sync(0xFFFFFFFFu, sum1, 1);
        sum1 += __shfl_xor_sync(0xFFFFFFFFu, sum1, 2);
        if (t == 0) { psum[wn][r0] = sum0; psum[wn][r1] = sum1; }
        __syncthreads();

        l[0] = l[0] * al0 + psum[0][r0] + psum[1][r0];
        l[1] = l[1] * al1 + psum[0][r1] + psum[1][r1];
        m[0] = mn0; m[1] = mn1;

#pragma unroll
        for (int j = 0; j < 16; j++) {
            o[j][0] *= al0; o[j][1] *= al0;
            o[j][2] *= al1; o[j][3] *= al1;
        }
#pragma unroll
        for (int kk2 = 0; kk2 < 2; kk2++) {
            unsigned aph[4], apl[4];
            aph[0] = h2u(s[2*kk2][0], s[2*kk2][1]);
            aph[1] = h2u(s[2*kk2][2], s[2*kk2][3]);
            aph[2] = h2u(s[2*kk2+1][0], s[2*kk2+1][1]);
            aph[3] = h2u(s[2*kk2+1][2], s[2*kk2+1][3]);
            apl[0] = h2lo(s[2*kk2][0], s[2*kk2][1], aph[0]);
            apl[1] = h2lo(s[2*kk2][2], s[2*kk2][3], aph[1]);
            apl[2] = h2lo(s[2*kk2+1][0], s[2*kk2+1][1], aph[2]);
            apl[3] = h2lo(s[2*kk2+1][2], s[2*kk2+1][3], aph[3]);
            const int col = wn * 32 + kk2 * 16 + 2 * t;
#pragma unroll
            for (int j2 = 0; j2 < 16; j2++) {
                int h = j2 * 8 + g;
                unsigned bh[2] = { *(unsigned*)&VTH[h][col], *(unsigned*)&VTH[h][col + 8] };
                unsigned bl[2] = { *(unsigned*)&VTL[h][col], *(unsigned*)&VTL[h][col + 8] };
                mma16816(o[j2], aph, bh);
                mma16816(o[j2], aph, bl);
                mma16816(o[j2], apl, bh);
            }
        }
    }

    float (*Ocomb)[132] = (float(*)[132])(smem + OFF_QH);
    __syncthreads();
    if (wn == 1) {
#pragma unroll
        for (int j2 = 0; j2 < 16; j2++) {
            int col = j2 * 8 + 2 * t;
            *(float2*)&Ocomb[r0][col] = make_float2(o[j2][0], o[j2][1]);
            *(float2*)&Ocomb[r1][col] = make_float2(o[j2][2], o[j2][3]);
        }
    }
    __syncthreads();
    if (wn == 0) {
        const float inv0 = 1.f / l[0], inv1 = 1.f / l[1];
        float* out0 = out + ((size_t)b * T + (size_t)qt * 64 + r0) * H;
        float* out1 = out + ((size_t)b * T + (size_t)qt * 64 + r1) * H;
#pragma unroll
        for (int j2 = 0; j2 < 16; j2++) {
            int col = j2 * 8 + 2 * t;
            *(float2*)(out0 + col) = make_float2((o[j2][0] + Ocomb[r0][col])     * inv0,
                                                 (o[j2][1] + Ocomb[r0][col + 1]) * inv0);
            *(float2*)(out1 + col) = make_float2((o[j2][2] + Ocomb[r1][col])     * inv1,
                                                 (o[j2][3] + Ocomb[r1][col + 1]) * inv1);
        }
    }
}

// ============================================================
extern "C" void kernel_launch(void* const* d_in, const int* in_sizes, int n_in,
                              void* d_out, int out_size)
{
    const float* x  = (const float*)d_in[0];
    const float* Wk = (const float*)d_in[1];
    const float* Wq = (const float*)d_in[2];
    const float* Wv = (const float*)d_in[3];
    float* out = (float*)d_out;

    cudaFuncSetAttribute(attn_kernel,
                         cudaFuncAttributeMaxDynamicSharedMemorySize, SMEM_ATTN);

    split_kernel<<<4096, 256>>>(x);
    wsplit_kernel<<<dim3(3, 32), 256>>>(Wk, Wq, Wv);
    proj_kernel<<<dim3(3, NROWS / 128), 256>>>();
    attn_kernel<<<256, 256, SMEM_ATTN>>>(out);
    (void)in_sizes; (void)n_in; (void)out_size;
}

// round 8
// speedup vs baseline: 3.3189x; 1.1291x over previous
#include <cuda_runtime.h>
#include <cuda_fp16.h>
#include <math_constants.h>
#include <cstdint>

#define Bsz 8
#define T   2048
#define C   1024
#define H   128
#define NROWS (Bsz * T)

// -------- gmem scratch (16B aligned) --------
__device__ __align__(16) __half g_xh[NROWS * C];
__device__ __align__(16) __half g_xl[NROWS * C];
__device__ __align__(16) __half g_wth[3 * H * C];
__device__ __align__(16) __half g_wtl[3 * H * C];
__device__ __align__(16) __half g_qh[NROWS * H];
__device__ __align__(16) __half g_ql[NROWS * H];
__device__ __align__(16) __half g_kh[NROWS * H];
__device__ __align__(16) __half g_kl[NROWS * H];
__device__ __align__(16) __half g_vth[Bsz * H * T];
__device__ __align__(16) __half g_vtl[Bsz * H * T];

// -------- helpers --------
__device__ __forceinline__ void mma16816(float* c, const unsigned* a, const unsigned* b) {
    asm volatile(
        "mma.sync.aligned.m16n8k16.row.col.f32.f16.f16.f32 "
        "{%0,%1,%2,%3}, {%4,%5,%6,%7}, {%8,%9}, {%0,%1,%2,%3};"
        : "+f"(c[0]), "+f"(c[1]), "+f"(c[2]), "+f"(c[3])
        : "r"(a[0]), "r"(a[1]), "r"(a[2]), "r"(a[3]), "r"(b[0]), "r"(b[1]));
}
__device__ __forceinline__ unsigned h2u(float x, float y) {
    __half2 h = __floats2half2_rn(x, y);
    return *reinterpret_cast<unsigned*>(&h);
}
__device__ __forceinline__ unsigned h2lo(float x, float y, unsigned hi) {
    __half2 h = *reinterpret_cast<__half2*>(&hi);
    float2 f = __half22float2(h);
    __half2 l = __floats2half2_rn(x - f.x, y - f.y);
    return *reinterpret_cast<unsigned*>(&l);
}
__device__ __forceinline__ void cpa16(uint32_t dst, const void* src) {
    asm volatile("cp.async.cg.shared.global [%0], [%1], 16;" :: "r"(dst), "l"(src));
}
#define CP_COMMIT() asm volatile("cp.async.commit_group;" ::: "memory")
#define CP_WAIT0()  asm volatile("cp.async.wait_group 0;" ::: "memory")

// ============================================================
// split_kernel: x (fp32) -> half hi/lo
// ============================================================
__global__ __launch_bounds__(256) void split_kernel(const float* __restrict__ x)
{
    const int tid = threadIdx.x;
#pragma unroll
    for (int i = 0; i < 4; i++) {
        unsigned u = blockIdx.x * 1024 + i * 256 + tid;
        float4 v = ((const float4*)x)[u];
        unsigned h0 = h2u(v.x, v.y), h1 = h2u(v.z, v.w);
        unsigned l0 = h2lo(v.x, v.y, h0), l1 = h2lo(v.z, v.w, h1);
        ((uint2*)g_xh)[u] = make_uint2(h0, h1);
        ((uint2*)g_xl)[u] = make_uint2(l0, l1);
    }
}

// ============================================================
// wsplit_kernel: W[k][n] -> W^T hi/lo [sel][n][k]
// ============================================================
__global__ __launch_bounds__(256) void wsplit_kernel(
    const float* __restrict__ Wk, const float* __restrict__ Wq,
    const float* __restrict__ Wv)
{
    __shared__ float ws[32][133];
    const int sel = blockIdx.x;
    const float* W = (sel == 0) ? Wk : (sel == 1) ? Wq : Wv;
    const int k0 = blockIdx.y * 32;
    const int tid = threadIdx.x;
#pragma unroll
    for (int i = 0; i < 16; i++) {
        int idx = tid + i * 256;
        int k = idx >> 7, n = idx & 127;
        ws[k][n] = W[(size_t)(k0 + k) * H + n];
    }
    __syncthreads();
    __half* wth = g_wth + (size_t)sel * H * C;
    __half* wtl = g_wtl + (size_t)sel * H * C;
#pragma unroll
    for (int i = 0; i < 16; i++) {
        int idx = tid + i * 256;
        int n = idx >> 5, kk = idx & 31;
        float v = ws[kk][n];
        __half h = __float2half_rn(v);
        wth[(size_t)n * C + k0 + kk] = h;
        wtl[(size_t)n * C + k0 + kk] = __float2half_rn(v - __half2float(h));
    }
}

// ============================================================
// Projection GEMM (HMMA fp16x3), cp.async double-buffered.
// ============================================================
#define PSTR 40                 // halves; 80B row stride (16B multiple)
#define PB_ARR 10240            // bytes per array tile (128 x 40 halves)
#define PB_SZ  40960            // 4 arrays
#define SMEM_PROJ 81920         // 2 buffers

__global__ __launch_bounds__(256, 2) void proj_kernel()
{
    extern __shared__ char smem[];
    const uint32_t sbase = (uint32_t)__cvta_generic_to_shared(smem);

    const int sel = blockIdx.x;
    const int m0 = blockIdx.y * 128;
    const int tid = threadIdx.x;
    const int w = tid >> 5, lane = tid & 31;
    const int wm = w & 3, wn = w >> 2;
    const int g = lane >> 2, t = lane & 3;

    const __half* src[4] = {
        g_xh + (size_t)m0 * C, g_xl + (size_t)m0 * C,
        g_wth + (size_t)sel * H * C, g_wtl + (size_t)sel * H * C };

    // per-thread load slots: 8 cp16 per buffer fill
    int larr[8], lrow[8], lc8[8];
#pragma unroll
    for (int i = 0; i < 8; i++) {
        int idx = tid + i * 256;
        larr[i] = idx >> 9;
        int j = idx & 511;
        lrow[i] = j >> 2;
        lc8[i]  = (j & 3) * 8;
    }

    // prologue: fill buffer 0 with k0 = 0
#pragma unroll
    for (int i = 0; i < 8; i++)
        cpa16(sbase + larr[i] * PB_ARR + lrow[i] * 80 + lc8[i] * 2,
              src[larr[i]] + (size_t)lrow[i] * C + lc8[i]);
    CP_COMMIT();

    float c[2][8][4];
#pragma unroll
    for (int mt = 0; mt < 2; mt++)
#pragma unroll
        for (int j = 0; j < 8; j++)
#pragma unroll
            for (int e = 0; e < 4; e++) c[mt][j][e] = 0.f;

    for (int ks = 0; ks < 32; ks++) {
        CP_WAIT0();
        __syncthreads();
        char* buf = smem + (ks & 1) * PB_SZ;
        if (ks < 31) {
            const uint32_t db = sbase + ((ks + 1) & 1) * PB_SZ;
            const int k1 = (ks + 1) * 32;
#pragma unroll
            for (int i = 0; i < 8; i++)
                cpa16(db + larr[i] * PB_ARR + lrow[i] * 80 + lc8[i] * 2,
                      src[larr[i]] + (size_t)lrow[i] * C + k1 + lc8[i]);
            CP_COMMIT();
        }
        __half (*Ah)[PSTR] = (__half(*)[PSTR])(buf);
        __half (*Al)[PSTR] = (__half(*)[PSTR])(buf + PB_ARR);
        __half (*Bh)[PSTR] = (__half(*)[PSTR])(buf + 2 * PB_ARR);
        __half (*Bl)[PSTR] = (__half(*)[PSTR])(buf + 3 * PB_ARR);

#pragma unroll
        for (int kk = 0; kk < 2; kk++) {
            const int col0 = kk * 16 + 2 * t;
            unsigned ah[2][4], al[2][4];
#pragma unroll
            for (int mt = 0; mt < 2; mt++) {
                int row = wm * 32 + mt * 16 + g;
                ah[mt][0] = *(unsigned*)&Ah[row][col0];
                ah[mt][1] = *(unsigned*)&Ah[row + 8][col0];
                ah[mt][2] = *(unsigned*)&Ah[row][col0 + 8];
                ah[mt][3] = *(unsigned*)&Ah[row + 8][col0 + 8];
                al[mt][0] = *(unsigned*)&Al[row][col0];
                al[mt][1] = *(unsigned*)&Al[row + 8][col0];
                al[mt][2] = *(unsigned*)&Al[row][col0 + 8];
                al[mt][3] = *(unsigned*)&Al[row + 8][col0 + 8];
            }
#pragma unroll
            for (int j = 0; j < 8; j++) {
                int n = wn * 64 + j * 8 + g;
                unsigned bh[2] = { *(unsigned*)&Bh[n][col0], *(unsigned*)&Bh[n][col0 + 8] };
                unsigned bl[2] = { *(unsigned*)&Bl[n][col0], *(unsigned*)&Bl[n][col0 + 8] };
#pragma unroll
                for (int mt = 0; mt < 2; mt++) {
                    mma16816(c[mt][j], ah[mt], bh);
                    mma16816(c[mt][j], ah[mt], bl);
                    mma16816(c[mt][j], al[mt], bh);
                }
            }
        }
    }

    // ---- fused split epilogue
    if (sel == 2) {
#pragma unroll
        for (int mt = 0; mt < 2; mt++)
#pragma unroll
            for (int j = 0; j < 8; j++) {
                int row0 = m0 + wm * 32 + mt * 16 + g;
                int col = wn * 64 + j * 8 + 2 * t;
#pragma unroll
                for (int e = 0; e < 4; e++) {
                    int row = row0 + (e >> 1) * 8;
                    int n = col + (e & 1);
                    float val = c[mt][j][e];
                    __half h = __float2half_rn(val);
                    size_t a = ((size_t)(row >> 11) * H + n) * T + (row & 2047);
                    g_vth[a] = h;
                    g_vtl[a] = __float2half_rn(val - __half2float(h));
                }
            }
    } else {
        __half* ghi = (sel == 0) ? g_kh : g_qh;
        __half* glo = (sel == 0) ? g_kl : g_ql;
        const float sc = (sel == 1) ? 32.f : 1.f;
#pragma unroll
        for (int mt = 0; mt < 2; mt++)
#pragma unroll
            for (int j = 0; j < 8; j++) {
                int row0 = m0 + wm * 32 + mt * 16 + g;
                int col = wn * 64 + j * 8 + 2 * t;
#pragma unroll
                for (int hr = 0; hr < 2; hr++) {
                    int row = row0 + hr * 8;
                    float v0 = c[mt][j][hr * 2] * sc;
                    float v1 = c[mt][j][hr * 2 + 1] * sc;
                    unsigned hi = h2u(v0, v1);
                    unsigned lo = h2lo(v0, v1, hi);
                    *(unsigned*)(ghi + (size_t)row * H + col) = hi;
                    *(unsigned*)(glo + (size_t)row * H + col) = lo;
                }
            }
    }
}

// ============================================================
// Flash attention (HMMA fp16x3), causal.
// Warp-local split-K softmax (no per-tile cross-warp exchange),
// cp.async double-buffered K/V. 1 syncthreads per tile.
// ============================================================
#define ASTR 136   // 272B row stride
#define VSTR 72    // 144B row stride

#define A_QH   0
#define A_QL   17408
#define A_KV0  34816
#define KV_KH  0
#define KV_KL  17408
#define KV_VTH 34816
#define KV_VTL 53248
#define KV_SZ  71680
#define A_PM   178176        // float[2][64]
#define A_PL   178688        // float[2][64]
#define SMEM_ATTN 179200

__global__ __launch_bounds__(256, 1) void attn_kernel(float* __restrict__ out)
{
    extern __shared__ char smem[];
    const uint32_t sbase = (uint32_t)__cvta_generic_to_shared(smem);

    const int tid = threadIdx.x;
    const int w = tid >> 5, lane = tid & 31;
    const int wm = w & 3, wn = w >> 2;
    const int g = lane >> 2, t = lane & 3;
    const int bx = blockIdx.x;
    const int b = bx & 7;
    const int qt = 31 - (bx >> 3);          // LPT

    const __half* QHg = g_qh + ((size_t)b * T + (size_t)qt * 64) * H;
    const __half* QLg = g_ql + ((size_t)b * T + (size_t)qt * 64) * H;
    const __half* KHg = g_kh + (size_t)b * T * H;
    const __half* KLg = g_kl + (size_t)b * T * H;
    const __half* VHg = g_vth + (size_t)b * H * T;
    const __half* VLg = g_vtl + (size_t)b * H * T;

    // ---- prologue: Q + KV tile 0 via cp.async
#pragma unroll
    for (int i = 0; i < 4; i++) {
        int idx = tid + i * 256;
        int row = idx >> 4, c8 = (idx & 15) * 8;
        cpa16(sbase + A_QH + row * 272 + c8 * 2, QHg + (size_t)row * H + c8);
        cpa16(sbase + A_QL + row * 272 + c8 * 2, QLg + (size_t)row * H + c8);
    }
    {
        const uint32_t kb = sbase + A_KV0;
#pragma unroll
        for (int i = 0; i < 4; i++) {
            int idx = tid + i * 256;
            int row = idx >> 4, c8 = (idx & 15) * 8;
            cpa16(kb + KV_KH + row * 272 + c8 * 2, KHg + (size_t)row * H + c8);
            cpa16(kb + KV_KL + row * 272 + c8 * 2, KLg + (size_t)row * H + c8);
            int vr = idx >> 3, v8 = (idx & 7) * 8;
            cpa16(kb + KV_VTH + vr * 144 + v8 * 2, VHg + (size_t)vr * T + v8);
            cpa16(kb + KV_VTL + vr * 144 + v8 * 2, VLg + (size_t)vr * T + v8);
        }
    }
    CP_COMMIT();

    __half (*QH)[ASTR] = (__half(*)[ASTR])(smem + A_QH);
    __half (*QL)[ASTR] = (__half(*)[ASTR])(smem + A_QL);

    const int r0 = wm * 16 + g, r1 = r0 + 8;
    float m[2] = {-1e30f, -1e30f}, l[2] = {0.f, 0.f};
    float o[16][4];
#pragma unroll
    for (int j = 0; j < 16; j++)
#pragma unroll
        for (int e = 0; e < 4; e++) o[j][e] = 0.f;

    for (int kt = 0; kt <= qt; kt++) {
        CP_WAIT0();
        __syncthreads();
        char* kv = smem + A_KV0 + (kt & 1) * KV_SZ;
        if (kt < qt) {
            const uint32_t kb = sbase + A_KV0 + ((kt + 1) & 1) * KV_SZ;
            const size_t koff = (size_t)(kt + 1) * 64;
#pragma unroll
            for (int i = 0; i < 4; i++) {
                int idx = tid + i * 256;
                int row = idx >> 4, c8 = (idx & 15) * 8;
                cpa16(kb + KV_KH + row * 272 + c8 * 2, KHg + (koff + row) * H + c8);
                cpa16(kb + KV_KL + row * 272 + c8 * 2, KLg + (koff + row) * H + c8);
                int vr = idx >> 3, v8 = (idx & 7) * 8;
                cpa16(kb + KV_VTH + vr * 144 + v8 * 2, VHg + (size_t)vr * T + koff + v8);
                cpa16(kb + KV_VTL + vr * 144 + v8 * 2, VLg + (size_t)vr * T + koff + v8);
            }
            CP_COMMIT();
        }
        __half (*KH)[ASTR]  = (__half(*)[ASTR])(kv + KV_KH);
        __half (*KL)[ASTR]  = (__half(*)[ASTR])(kv + KV_KL);
        __half (*VTH)[VSTR] = (__half(*)[VSTR])(kv + KV_VTH);
        __half (*VTL)[VSTR] = (__half(*)[VSTR])(kv + KV_VTL);

        // ---- S = Q K^T (3-pass), warp: rows [r0,r1], cols wn*32..+31
        float s[4][4];
#pragma unroll
        for (int j = 0; j < 4; j++)
#pragma unroll
            for (int e = 0; e < 4; e++) s[j][e] = 0.f;

#pragma unroll
        for (int kk = 0; kk < 8; kk++) {
            const int col0 = kk * 16 + 2 * t;
            unsigned ah[4], al[4];
            ah[0] = *(unsigned*)&QH[r0][col0];
            ah[1] = *(unsigned*)&QH[r1][col0];
            ah[2] = *(unsigned*)&QH[r0][col0 + 8];
            ah[3] = *(unsigned*)&QH[r1][col0 + 8];
            al[0] = *(unsigned*)&QL[r0][col0];
            al[1] = *(unsigned*)&QL[r1][col0];
            al[2] = *(unsigned*)&QL[r0][col0 + 8];
            al[3] = *(unsigned*)&QL[r1][col0 + 8];
#pragma unroll
            for (int j = 0; j < 4; j++) {
                int n = wn * 32 + j * 8 + g;
                unsigned bh[2] = { *(unsigned*)&KH[n][col0], *(unsigned*)&KH[n][col0 + 8] };
                unsigned bl[2] = { *(unsigned*)&KL[n][col0], *(unsigned*)&KL[n][col0 + 8] };
                mma16816(s[j], ah, bh);
                mma16816(s[j], ah, bl);
                mma16816(s[j], al, bh);
            }
        }

        if (kt == qt) {
#pragma unroll
            for (int j = 0; j < 4; j++) {
                int cl = wn * 32 + j * 8 + 2 * t;
                if (cl     > r0) s[j][0] = -3e38f;
                if (cl + 1 > r0) s[j][1] = -3e38f;
                if (cl     > r1) s[j][2] = -3e38f;
                if (cl + 1 > r1) s[j][3] = -3e38f;
            }
        }

        // ---- warp-local online softmax (no cross-warp exchange)
        float mx0 = -3e38f, mx1 = -3e38f;
#pragma unroll
        for (int j = 0; j < 4; j++) {
            mx0 = fmaxf(mx0, fmaxf(s[j][0], s[j][1]));
            mx1 = fmaxf(mx1, fmaxf(s[j][2], s[j][3]));
        }
        mx0 = fmaxf(mx0, __shfl_xor_sync(0xFFFFFFFFu, mx0, 1));
        mx0 = fmaxf(mx0, __shfl_xor_sync(0xFFFFFFFFu, mx0, 2));
        mx1 = fmaxf(mx1, __shfl_xor_sync(0xFFFFFFFFu, mx1, 1));
        mx1 = fmaxf(mx1, __shfl_xor_sync(0xFFFFFFFFu, mx1, 2));

        float mn0 = fmaxf(m[0], mx0);
        float mn1 = fmaxf(m[1], mx1);
        float al0 = __expf(m[0] - mn0);
        float al1 = __expf(m[1] - mn1);

        float sum0 = 0.f, sum1 = 0.f;
#pragma unroll
        for (int j = 0; j < 4; j++) {
            s[j][0] = __expf(s[j][0] - mn0);
            s[j][1] = __expf(s[j][1] - mn0);
            s[j][2] = __expf(s[j][2] - mn1);
            s[j][3] = __expf(s[j][3] - mn1);
            sum0 += s[j][0] + s[j][1];
            sum1 += s[j][2] + s[j][3];
        }
        sum0 += __shfl_xor_sync(0xFFFFFFFFu, sum0, 1);
        sum0 += __shfl_xor_sync(0xFFFFFFFFu, sum0, 2);
        sum1 += __shfl_xor_sync(0xFFFFFFFFu, sum1, 1);
        sum1 += __shfl_xor_sync(0xFFFFFFFFu, sum1, 2);

        l[0] = l[0] * al0 + sum0;
        l[1] = l[1] * al1 + sum1;
        m[0] = mn0; m[1] = mn1;

#pragma unroll
        for (int j = 0; j < 16; j++) {
            o[j][0] *= al0; o[j][1] *= al0;
            o[j][2] *= al1; o[j][3] *= al1;
        }
#pragma unroll
        for (int kk2 = 0; kk2 < 2; kk2++) {
            unsigned aph[4], apl[4];
            aph[0] = h2u(s[2*kk2][0], s[2*kk2][1]);
            aph[1] = h2u(s[2*kk2][2], s[2*kk2][3]);
            aph[2] = h2u(s[2*kk2+1][0], s[2*kk2+1][1]);
            aph[3] = h2u(s[2*kk2+1][2], s[2*kk2+1][3]);
            apl[0] = h2lo(s[2*kk2][0], s[2*kk2][1], aph[0]);
            apl[1] = h2lo(s[2*kk2][2], s[2*kk2][3], aph[1]);
            apl[2] = h2lo(s[2*kk2+1][0], s[2*kk2+1][1], aph[2]);
            apl[3] = h2lo(s[2*kk2+1][2], s[2*kk2+1][3], aph[3]);
            const int col = wn * 32 + kk2 * 16 + 2 * t;
#pragma unroll
            for (int j2 = 0; j2 < 16; j2++) {
                int h = j2 * 8 + g;
                unsigned bh[2] = { *(unsigned*)&VTH[h][col], *(unsigned*)&VTH[h][col + 8] };
                unsigned bl[2] = { *(unsigned*)&VTL[h][col], *(unsigned*)&VTL[h][col + 8] };
                mma16816(o[j2], aph, bh);
                mma16816(o[j2], aph, bl);
                mma16816(o[j2], apl, bh);
            }
        }
    }

    // ---- final split-K combine across the two wn halves
    float* pm = (float*)(smem + A_PM);   // [2][64]
    float* pl = (float*)(smem + A_PL);
    __syncthreads();
    if (t == 0) {
        pm[wn * 64 + r0] = m[0]; pm[wn * 64 + r1] = m[1];
        pl[wn * 64 + r0] = l[0]; pl[wn * 64 + r1] = l[1];
    }
    __syncthreads();
    float M0 = fmaxf(pm[r0], pm[64 + r0]);
    float M1 = fmaxf(pm[r1], pm[64 + r1]);
    float L0 = pl[r0] * __expf(pm[r0] - M0) + pl[64 + r0] * __expf(pm[64 + r0] - M0);
    float L1 = pl[r1] * __expf(pm[r1] - M1) + pl[64 + r1] * __expf(pm[64 + r1] - M1);
    float c0 = __expf(m[0] - M0);
    float c1 = __expf(m[1] - M1);

    float (*Ocomb)[132] = (float(*)[132])(smem + A_QH);   // overlay dead Q area
    if (wn == 1) {
#pragma unroll
        for (int j2 = 0; j2 < 16; j2++) {
            int col = j2 * 8 + 2 * t;
            *(float2*)&Ocomb[r0][col] = make_float2(o[j2][0] * c0, o[j2][1] * c0);
            *(float2*)&Ocomb[r1][col] = make_float2(o[j2][2] * c1, o[j2][3] * c1);
        }
    }
    __syncthreads();
    if (wn == 0) {
        const float inv0 = 1.f / L0, inv1 = 1.f / L1;
        float* out0 = out + ((size_t)b * T + (size_t)qt * 64 + r0) * H;
        float* out1 = out + ((size_t)b * T + (size_t)qt * 64 + r1) * H;
#pragma unroll
        for (int j2 = 0; j2 < 16; j2++) {
            int col = j2 * 8 + 2 * t;
            *(float2*)(out0 + col) = make_float2((o[j2][0] * c0 + Ocomb[r0][col])     * inv0,
                                                 (o[j2][1] * c0 + Ocomb[r0][col + 1]) * inv0);
            *(float2*)(out1 + col) = make_float2((o[j2][2] * c1 + Ocomb[r1][col])     * inv1,
                                                 (o[j2][3] * c1 + Ocomb[r1][col + 1]) * inv1);
        }
    }
}

// ============================================================
extern "C" void kernel_launch(void* const* d_in, const int* in_sizes, int n_in,
                              void* d_out, int out_size)
{
    const float* x  = (const float*)d_in[0];
    const float* Wk = (const float*)d_in[1];
    const float* Wq = (const float*)d_in[2];
    const float* Wv = (const float*)d_in[3];
    float* out = (float*)d_out;

    cudaFuncSetAttribute(proj_kernel,
                         cudaFuncAttributeMaxDynamicSharedMemorySize, SMEM_PROJ);
    cudaFuncSetAttribute(attn_kernel,
                         cudaFuncAttributeMaxDynamicSharedMemorySize, SMEM_ATTN);

    split_kernel<<<4096, 256>>>(x);
    wsplit_kernel<<<dim3(3, 32), 256>>>(Wk, Wq, Wv);
    proj_kernel<<<dim3(3, NROWS / 128), 256, SMEM_PROJ>>>();
    attn_kernel<<<256, 256, SMEM_ATTN>>>(out);
    (void)in_sizes; (void)n_in; (void)out_size;
}